// round 1
// baseline (speedup 1.0000x reference)
#include <cuda_runtime.h>
#include <cstdint>

#define B_  4
#define S_  1024
#define D_  1024
#define H_  16
#define HD_ 64
#define MTOT (B_*S_)        // 4096

// ---------------------------------------------------------------------------
// Static scratch (no allocations allowed)
// ---------------------------------------------------------------------------
__device__ float g_q[MTOT*D_];
__device__ float g_k[MTOT*D_];
__device__ float g_v[MTOT*D_];
__device__ float g_ao[MTOT*D_];
__device__ float g_attn_fb[(size_t)B_*H_*S_*S_];   // fallback if attn not in d_out
__device__ float g_out_fb[MTOT*D_];                // fallback if output not in d_out

// ---------------------------------------------------------------------------
// Multi-threshold neuron (fresh state): mem = x/2; thresholds 1,2,3,4
// ---------------------------------------------------------------------------
__device__ __forceinline__ float mtn_f(float x, float n0, float n1, float n2, float n3)
{
    float mem = x * 0.5f;
    float s = 0.f;
    if (mem >= 1.f) { s += n0; mem -= 1.f; }
    if (mem >= 2.f) { s += n1; mem -= 2.f; }
    if (mem >= 3.f) { s += n2; mem -= 3.f; }
    if (mem >= 4.f) { s += n3; mem -= 4.f; }
    return s;
}

// ---------------------------------------------------------------------------
// fp32 SGEMM: C[m,n] = sum_k A[m,k] * W[n,k] + bias[n]   (both K-major, NT)
// optional MTN epilogue. Tiles 128x128x8, 256 threads, 8x8 per thread.
// M,N multiples of 128; K multiple of 8.
// ---------------------------------------------------------------------------
__global__ __launch_bounds__(256) void sgemm_nt_bias(
    const float* __restrict__ A, const float* __restrict__ W,
    const float* __restrict__ bias, const float* __restrict__ nw,
    float* __restrict__ C, int M, int N, int K, int do_mtn)
{
    __shared__ __align__(16) float As[8][128];
    __shared__ __align__(16) float Ws[8][128];
    const int tid = threadIdx.x;
    const int bm = blockIdx.y * 128;
    const int bn = blockIdx.x * 128;
    const int lr = tid >> 1;           // 0..127
    const int lc = (tid & 1) * 4;      // 0 or 4
    const float* Ap = A + (size_t)(bm + lr) * K + lc;
    const float* Wp = W + (size_t)(bn + lr) * K + lc;
    const int tx = tid & 15, ty = tid >> 4;

    float acc[8][8];
    #pragma unroll
    for (int i = 0; i < 8; i++)
        #pragma unroll
        for (int j = 0; j < 8; j++) acc[i][j] = 0.f;

    for (int k0 = 0; k0 < K; k0 += 8) {
        float4 a4 = *reinterpret_cast<const float4*>(Ap + k0);
        float4 w4 = *reinterpret_cast<const float4*>(Wp + k0);
        __syncthreads();
        As[lc+0][lr] = a4.x; As[lc+1][lr] = a4.y; As[lc+2][lr] = a4.z; As[lc+3][lr] = a4.w;
        Ws[lc+0][lr] = w4.x; Ws[lc+1][lr] = w4.y; Ws[lc+2][lr] = w4.z; Ws[lc+3][lr] = w4.w;
        __syncthreads();
        #pragma unroll
        for (int kk = 0; kk < 8; kk++) {
            float4 a0 = *reinterpret_cast<const float4*>(&As[kk][ty*8]);
            float4 a1 = *reinterpret_cast<const float4*>(&As[kk][ty*8+4]);
            float4 w0 = *reinterpret_cast<const float4*>(&Ws[kk][tx*8]);
            float4 w1 = *reinterpret_cast<const float4*>(&Ws[kk][tx*8+4]);
            float ar[8] = {a0.x,a0.y,a0.z,a0.w,a1.x,a1.y,a1.z,a1.w};
            float wr[8] = {w0.x,w0.y,w0.z,w0.w,w1.x,w1.y,w1.z,w1.w};
            #pragma unroll
            for (int i = 0; i < 8; i++)
                #pragma unroll
                for (int j = 0; j < 8; j++)
                    acc[i][j] = fmaf(ar[i], wr[j], acc[i][j]);
        }
    }

    float n0 = 0.f, n1 = 0.f, n2 = 0.f, n3 = 0.f;
    if (do_mtn) { n0 = nw[0]*0.25f; n1 = nw[1]*0.25f; n2 = nw[2]*0.25f; n3 = nw[3]*0.25f; }

    #pragma unroll
    for (int i = 0; i < 8; i++) {
        const int m = bm + ty*8 + i;
        #pragma unroll
        for (int j = 0; j < 8; j++) {
            const int n = bn + tx*8 + j;
            float v = acc[i][j] + bias[n];
            if (do_mtn) v = mtn_f(v, n0, n1, n2, n3);
            C[(size_t)m * N + n] = v;
        }
    }
}

// ---------------------------------------------------------------------------
// ECM compensation, in place, exploiting post-MTN sparsity:
//   X[s,n] <- X[s,n] + bc[n] - sum_{j : X[s,j]!=0} X[s,j] * Wc[n,j]
// One block per row. Expected nonzeros per row ~ 1.
// ---------------------------------------------------------------------------
__global__ __launch_bounds__(256) void comp_inplace(
    float* __restrict__ X, const float* __restrict__ Wc, const float* __restrict__ bc)
{
    __shared__ float row[1024];
    __shared__ int   nzi[1024];
    __shared__ float nzv[1024];
    __shared__ int   cnt;
    const int tid = threadIdx.x;
    float* xr = X + (size_t)blockIdx.x * D_;
    if (tid == 0) cnt = 0;
    __syncthreads();
    for (int j = tid; j < D_; j += 256) {
        float v = xr[j];
        row[j] = v;
        if (v != 0.f) { int p = atomicAdd(&cnt, 1); nzi[p] = j; nzv[p] = v; }
    }
    __syncthreads();
    const int c = cnt;
    for (int n = tid; n < D_; n += 256) {
        float acc = row[n] + bc[n];
        const float* wrow = Wc + (size_t)n * D_;
        for (int t = 0; t < c; t++)
            acc = fmaf(-nzv[t], wrow[nzi[t]], acc);
        xr[n] = acc;
    }
}

// ---------------------------------------------------------------------------
// scores[z, sq, sk] = (q[b,sq,h*64:] . k[b,sk,h*64:]) * 0.125 / (temp + 1e-8)
// z = b*16 + h. Tiles 64x64, K=64 in one shot. 256 threads, 4x4 per thread.
// ---------------------------------------------------------------------------
__global__ __launch_bounds__(256) void scores_kernel(
    const float* __restrict__ Q, const float* __restrict__ Kt,
    const float* __restrict__ temp, float* __restrict__ attn)
{
    __shared__ __align__(16) float Qs[64][64];   // [d][s]
    __shared__ __align__(16) float Ks[64][64];
    const int tid = threadIdx.x;
    const int z = blockIdx.z;
    const int b = z >> 4, h = z & 15;
    const int sq0 = blockIdx.y * 64, sk0 = blockIdx.x * 64;
    const int c4 = tid & 15;
    const int r0 = tid >> 4;
    #pragma unroll
    for (int pass = 0; pass < 4; pass++) {
        const int r = r0 + pass * 16;
        float4 q4 = *reinterpret_cast<const float4*>(Q + (size_t)(b*S_ + sq0 + r)*D_ + h*HD_ + c4*4);
        float4 k4 = *reinterpret_cast<const float4*>(Kt + (size_t)(b*S_ + sk0 + r)*D_ + h*HD_ + c4*4);
        Qs[c4*4+0][r] = q4.x; Qs[c4*4+1][r] = q4.y; Qs[c4*4+2][r] = q4.z; Qs[c4*4+3][r] = q4.w;
        Ks[c4*4+0][r] = k4.x; Ks[c4*4+1][r] = k4.y; Ks[c4*4+2][r] = k4.z; Ks[c4*4+3][r] = k4.w;
    }
    __syncthreads();
    const int tx = tid & 15, ty = tid >> 4;
    float acc[4][4] = {};
    #pragma unroll
    for (int d = 0; d < 64; d++) {
        float4 q4 = *reinterpret_cast<const float4*>(&Qs[d][ty*4]);
        float4 k4 = *reinterpret_cast<const float4*>(&Ks[d][tx*4]);
        float qa[4] = {q4.x,q4.y,q4.z,q4.w};
        float ka[4] = {k4.x,k4.y,k4.z,k4.w};
        #pragma unroll
        for (int i = 0; i < 4; i++)
            #pragma unroll
            for (int j = 0; j < 4; j++)
                acc[i][j] = fmaf(qa[i], ka[j], acc[i][j]);
    }
    const float t = temp[0];
    const float f = 0.125f / (t + 1e-8f);
    #pragma unroll
    for (int i = 0; i < 4; i++)
        #pragma unroll
        for (int j = 0; j < 4; j++)
            attn[((size_t)z*S_ + sq0 + ty*4 + i)*S_ + sk0 + tx*4 + j] = acc[i][j] * f;
}

// ---------------------------------------------------------------------------
// Row softmax, in place, one block per 1024-wide row
// ---------------------------------------------------------------------------
__global__ __launch_bounds__(256) void softmax_kernel(float* __restrict__ attn)
{
    __shared__ float red[8];
    const int tid = threadIdx.x;
    float* p = attn + (size_t)blockIdx.x * 1024;
    float v[4];
    #pragma unroll
    for (int i = 0; i < 4; i++) v[i] = p[tid + i*256];
    float m = fmaxf(fmaxf(v[0], v[1]), fmaxf(v[2], v[3]));
    #pragma unroll
    for (int o = 16; o > 0; o >>= 1) m = fmaxf(m, __shfl_xor_sync(0xffffffffu, m, o));
    if ((tid & 31) == 0) red[tid >> 5] = m;
    __syncthreads();
    m = red[0];
    #pragma unroll
    for (int i = 1; i < 8; i++) m = fmaxf(m, red[i]);
    float e[4]; float s = 0.f;
    #pragma unroll
    for (int i = 0; i < 4; i++) { e[i] = expf(v[i] - m); s += e[i]; }
    #pragma unroll
    for (int o = 16; o > 0; o >>= 1) s += __shfl_xor_sync(0xffffffffu, s, o);
    __syncthreads();
    if ((tid & 31) == 0) red[tid >> 5] = s;
    __syncthreads();
    s = 0.f;
    #pragma unroll
    for (int i = 0; i < 8; i++) s += red[i];
    #pragma unroll
    for (int i = 0; i < 4; i++) p[tid + i*256] = e[i] / s;
}

// ---------------------------------------------------------------------------
// attn_out[b, sq, h*64+n] = sum_sk attn[z, sq, sk] * v[b, sk, h*64+n]
// Tiles 64 rows x 64 cols (full hd), K chunks of 32. 4x4 per thread.
// ---------------------------------------------------------------------------
__global__ __launch_bounds__(256) void attnv_kernel(
    const float* __restrict__ attn, const float* __restrict__ V, float* __restrict__ out)
{
    __shared__ __align__(16) float As[32][64];   // [kk][row]
    __shared__ __align__(16) float Vs[32][64];   // [kk][n]
    const int tid = threadIdx.x;
    const int z = blockIdx.y;
    const int b = z >> 4, h = z & 15;
    const int sq0 = blockIdx.x * 64;
    const int lr = tid >> 2, lc = (tid & 3) * 8;     // attn tile 64x32
    const int vr = tid >> 3, vc = (tid & 7) * 8;     // v tile 32x64
    const int tx = tid & 15, ty = tid >> 4;
    const float* ap = attn + ((size_t)z*S_ + sq0) * S_;
    float acc[4][4] = {};

    for (int k0 = 0; k0 < S_; k0 += 32) {
        float4 x0 = *reinterpret_cast<const float4*>(ap + (size_t)lr*S_ + k0 + lc);
        float4 x1 = *reinterpret_cast<const float4*>(ap + (size_t)lr*S_ + k0 + lc + 4);
        float4 v0 = *reinterpret_cast<const float4*>(V + (size_t)(b*S_ + k0 + vr)*D_ + h*HD_ + vc);
        float4 v1 = *reinterpret_cast<const float4*>(V + (size_t)(b*S_ + k0 + vr)*D_ + h*HD_ + vc + 4);
        __syncthreads();
        As[lc+0][lr] = x0.x; As[lc+1][lr] = x0.y; As[lc+2][lr] = x0.z; As[lc+3][lr] = x0.w;
        As[lc+4][lr] = x1.x; As[lc+5][lr] = x1.y; As[lc+6][lr] = x1.z; As[lc+7][lr] = x1.w;
        *reinterpret_cast<float4*>(&Vs[vr][vc])   = v0;
        *reinterpret_cast<float4*>(&Vs[vr][vc+4]) = v1;
        __syncthreads();
        #pragma unroll
        for (int kk = 0; kk < 32; kk++) {
            float4 a4 = *reinterpret_cast<const float4*>(&As[kk][ty*4]);
            float4 w4 = *reinterpret_cast<const float4*>(&Vs[kk][tx*4]);
            float aa[4] = {a4.x,a4.y,a4.z,a4.w};
            float ww[4] = {w4.x,w4.y,w4.z,w4.w};
            #pragma unroll
            for (int i = 0; i < 4; i++)
                #pragma unroll
                for (int j = 0; j < 4; j++)
                    acc[i][j] = fmaf(aa[i], ww[j], acc[i][j]);
        }
    }
    #pragma unroll
    for (int i = 0; i < 4; i++)
        #pragma unroll
        for (int j = 0; j < 4; j++)
            out[(size_t)(b*S_ + sq0 + ty*4 + i)*D_ + h*HD_ + tx*4 + j] = acc[i][j];
}

// ---------------------------------------------------------------------------
// Launch
// ---------------------------------------------------------------------------
extern "C" void kernel_launch(void* const* d_in, const int* in_sizes, int n_in,
                              void* d_out, int out_size)
{
    const float* query = (const float*)d_in[0];
    const float* key   = (const float*)d_in[1];
    const float* value = (const float*)d_in[2];
    const float* Wq  = (const float*)d_in[3];
    const float* bq  = (const float*)d_in[4];
    const float* Wk  = (const float*)d_in[5];
    const float* bk  = (const float*)d_in[6];
    const float* Wv  = (const float*)d_in[7];
    const float* bv  = (const float*)d_in[8];
    const float* Wo  = (const float*)d_in[9];
    const float* bo  = (const float*)d_in[10];
    const float* Wqc = (const float*)d_in[11];
    const float* bqc = (const float*)d_in[12];
    const float* Wkc = (const float*)d_in[13];
    const float* bkc = (const float*)d_in[14];
    const float* Wvc = (const float*)d_in[15];
    const float* bvc = (const float*)d_in[16];
    const float* nw_q = (const float*)d_in[17];
    const float* nw_k = (const float*)d_in[18];
    const float* nw_v = (const float*)d_in[19];
    const float* nw_o = (const float*)d_in[20];
    const float* temperature = (const float*)d_in[21];

    float *q, *k, *v, *ao, *attn_fb, *out_fb;
    cudaGetSymbolAddress((void**)&q,  g_q);
    cudaGetSymbolAddress((void**)&k,  g_k);
    cudaGetSymbolAddress((void**)&v,  g_v);
    cudaGetSymbolAddress((void**)&ao, g_ao);
    cudaGetSymbolAddress((void**)&attn_fb, g_attn_fb);
    cudaGetSymbolAddress((void**)&out_fb,  g_out_fb);

    const size_t NOUT = (size_t)MTOT * D_;           // 4,194,304
    const size_t NATT = (size_t)B_ * H_ * S_ * S_;   // 67,108,864
    float* out = (float*)d_out;
    float* out_ptr;
    float* attn_ptr;
    const size_t osz = (size_t)out_size;
    if (osz == NOUT + NATT)      { out_ptr = out;    attn_ptr = out + NOUT; }
    else if (osz == NOUT)        { out_ptr = out;    attn_ptr = attn_fb;    }
    else if (osz == NATT)        { out_ptr = out_fb; attn_ptr = out;        }
    else                         { out_ptr = out;    attn_ptr = out + NOUT; }

    dim3 gg(D_/128, MTOT/128);   // (8, 32)

    // Spiking projections (GEMM + bias + MTN)
    sgemm_nt_bias<<<gg, 256>>>(query, Wq, bq, nw_q, q, MTOT, D_, D_, 1);
    sgemm_nt_bias<<<gg, 256>>>(key,   Wk, bk, nw_k, k, MTOT, D_, D_, 1);
    sgemm_nt_bias<<<gg, 256>>>(value, Wv, bv, nw_v, v, MTOT, D_, D_, 1);

    // ECM compensation (sparse, in place)
    comp_inplace<<<MTOT, 256>>>(q, Wqc, bqc);
    comp_inplace<<<MTOT, 256>>>(k, Wkc, bkc);
    comp_inplace<<<MTOT, 256>>>(v, Wvc, bvc);

    // Attention
    scores_kernel<<<dim3(S_/64, S_/64, B_*H_), 256>>>(q, k, temperature, attn_ptr);
    softmax_kernel<<<B_*H_*S_, 256>>>(attn_ptr);
    attnv_kernel<<<dim3(S_/64, B_*H_), 256>>>(attn_ptr, v, ao);

    // Output projection + MTN
    sgemm_nt_bias<<<gg, 256>>>(ao, Wo, bo, nw_o, out_ptr, MTOT, D_, D_, 1);
}

// round 3
// speedup vs baseline: 2.4405x; 2.4405x over previous
#include <cuda_runtime.h>
#include <cuda_bf16.h>
#include <cstdint>

#define B_  4
#define S_  1024
#define D_  1024
#define H_  16
#define HD_ 64
#define MTOT (B_*S_)        // 4096

// ---------------------------------------------------------------------------
// Static scratch
// ---------------------------------------------------------------------------
__device__ float g_q[MTOT*D_];
__device__ float g_k[MTOT*D_];
__device__ float g_v[MTOT*D_];
__device__ float g_ao[MTOT*D_];
__device__ float g_attn_fb[(size_t)B_*H_*S_*S_];
__device__ float g_out_fb[MTOT*D_];
__device__ __nv_bfloat16 g_Wh[(size_t)4*D_*D_];   // pre-split weight hi
__device__ __nv_bfloat16 g_Wl[(size_t)4*D_*D_];   // pre-split weight lo
__device__ float g_WcT[(size_t)3*D_*D_];          // transposed comp weights

// ---------------------------------------------------------------------------
// Helpers
// ---------------------------------------------------------------------------
__device__ __forceinline__ uint32_t smem_u32(const void* p) {
    uint32_t a;
    asm("{ .reg .u64 t; cvta.to.shared.u64 t, %1; cvt.u32.u64 %0, t; }" : "=r"(a) : "l"(p));
    return a;
}
__device__ __forceinline__ uint32_t swz(uint32_t off) { return off ^ ((off >> 3) & 0x70); }

__device__ __forceinline__ void ldsm4(uint32_t& r0, uint32_t& r1, uint32_t& r2, uint32_t& r3, uint32_t a) {
    asm volatile("ldmatrix.sync.aligned.m8n8.x4.shared.b16 {%0,%1,%2,%3}, [%4];"
                 : "=r"(r0), "=r"(r1), "=r"(r2), "=r"(r3) : "r"(a));
}
__device__ __forceinline__ void ldsm4t(uint32_t& r0, uint32_t& r1, uint32_t& r2, uint32_t& r3, uint32_t a) {
    asm volatile("ldmatrix.sync.aligned.m8n8.x4.trans.shared.b16 {%0,%1,%2,%3}, [%4];"
                 : "=r"(r0), "=r"(r1), "=r"(r2), "=r"(r3) : "r"(a));
}
__device__ __forceinline__ void mma16816(float* c, const uint32_t* a, const uint32_t* b) {
    asm volatile("mma.sync.aligned.m16n8k16.row.col.f32.bf16.bf16.f32 "
                 "{%0,%1,%2,%3}, {%4,%5,%6,%7}, {%8,%9}, {%0,%1,%2,%3};"
                 : "+f"(c[0]), "+f"(c[1]), "+f"(c[2]), "+f"(c[3])
                 : "r"(a[0]), "r"(a[1]), "r"(a[2]), "r"(a[3]), "r"(b[0]), "r"(b[1]));
}
__device__ __forceinline__ void cpasync16(uint32_t sdst, const void* g) {
    asm volatile("cp.async.ca.shared.global [%0], [%1], 16;" :: "r"(sdst), "l"(g) : "memory");
}
#define CP_COMMIT() asm volatile("cp.async.commit_group;" ::: "memory")
#define CP_WAIT0()  asm volatile("cp.async.wait_group 0;" ::: "memory")

__device__ __forceinline__ void split2(float x, float y, uint32_t& hi, uint32_t& lo) {
    __nv_bfloat16 hx = __float2bfloat16(x), hy = __float2bfloat16(y);
    __nv_bfloat16 lx = __float2bfloat16(x - __bfloat162float(hx));
    __nv_bfloat16 ly = __float2bfloat16(y - __bfloat162float(hy));
    hi = ((uint32_t)__bfloat16_as_ushort(hy) << 16) | (uint32_t)__bfloat16_as_ushort(hx);
    lo = ((uint32_t)__bfloat16_as_ushort(ly) << 16) | (uint32_t)__bfloat16_as_ushort(lx);
}
__device__ __forceinline__ uint32_t pack_hi(float x, float y) {
    return ((uint32_t)__bfloat16_as_ushort(__float2bfloat16(y)) << 16)
         |  (uint32_t)__bfloat16_as_ushort(__float2bfloat16(x));
}

__device__ __forceinline__ float mtn_f(float x, float n0, float n1, float n2, float n3) {
    float mem = x * 0.5f;
    float s = 0.f;
    if (mem >= 1.f) { s += n0; mem -= 1.f; }
    if (mem >= 2.f) { s += n1; mem -= 2.f; }
    if (mem >= 3.f) { s += n2; mem -= 3.f; }
    if (mem >= 4.f) { s += n3; mem -= 4.f; }
    return s;
}

// ---------------------------------------------------------------------------
// Projection GEMM (HMMA): C[4096,1024] = mtn(A @ W^T + bias)
// Block 128x128, 8 warps (2x4), warp 64x32, K chunks of 64, double-buffered.
// np3: 3-pass bf16 split (hh+hl+lh) when 1, single hi pass when 0.
// dyn smem: 2 stages x (Ah 16K | Al 16K | Bh 16K | Bl 16K) + 1K align
// ---------------------------------------------------------------------------
__global__ __launch_bounds__(256) void proj_hmma(
    const float* __restrict__ A, const __nv_bfloat16* __restrict__ Wh,
    const __nv_bfloat16* __restrict__ Wl, const float* __restrict__ bias,
    const float* __restrict__ nw, float* __restrict__ C, int np3)
{
    extern __shared__ char sraw[];
    const uint32_t sb0 = smem_u32(sraw);
    const uint32_t sbase = (sb0 + 1023) & ~1023u;
    char* sm = sraw + (sbase - sb0);
    const int tid = threadIdx.x, lane = tid & 31, wid = tid >> 5;
    const int wm = wid >> 2, wn = wid & 3;
    const int bm = blockIdx.y * 128, bn = blockIdx.x * 128;

    float acc[4][4][4];
    #pragma unroll
    for (int i = 0; i < 4; i++)
        #pragma unroll
        for (int j = 0; j < 4; j++)
            #pragma unroll
            for (int t = 0; t < 4; t++) acc[i][j][t] = 0.f;

    float4 av[8];

    auto ldgA = [&](int c) {
        #pragma unroll
        for (int i = 0; i < 8; i++) {
            int idx = tid + i * 256, r = idx >> 4, c4 = (idx & 15) * 4;
            av[i] = *(const float4*)(A + (size_t)(bm + r) * D_ + c * 64 + c4);
        }
    };
    auto stsA = [&](int stg) {
        char* dst = sm + stg * 65536;
        #pragma unroll
        for (int i = 0; i < 8; i++) {
            int idx = tid + i * 256, r = idx >> 4, c4 = (idx & 15) * 4;
            uint32_t h0, l0, h1, l1;
            split2(av[i].x, av[i].y, h0, l0);
            split2(av[i].z, av[i].w, h1, l1);
            uint32_t off = swz((uint32_t)(r * 128 + c4 * 2));
            *(uint2*)(dst + off) = make_uint2(h0, h1);
            if (np3) *(uint2*)(dst + 16384 + off) = make_uint2(l0, l1);
        }
    };
    auto cpW = [&](int c, int stg) {
        uint32_t base = sbase + stg * 65536 + 32768;
        #pragma unroll
        for (int i = 0; i < 4; i++) {
            int idx = tid + i * 256, r = idx >> 3, c8 = (idx & 7) * 8;
            uint32_t off = swz((uint32_t)(r * 128 + c8 * 2));
            cpasync16(base + off, Wh + (size_t)(bn + r) * D_ + c * 64 + c8);
            if (np3) cpasync16(base + 16384 + off, Wl + (size_t)(bn + r) * D_ + c * 64 + c8);
        }
        CP_COMMIT();
    };
    auto compute = [&](int stg) {
        uint32_t aB = sbase + stg * 65536;
        uint32_t bB = aB + 32768;
        #pragma unroll
        for (int ks = 0; ks < 4; ks++) {
            const uint32_t kcol = (uint32_t)((ks * 16 + ((lane >> 4) << 3)) * 2);
            uint32_t ah[4][4], al[4][4], bh[4][2], bl[4][2];
            #pragma unroll
            for (int mi = 0; mi < 4; mi++) {
                uint32_t off = swz((uint32_t)((wm * 64 + mi * 16 + (lane & 15)) * 128) + kcol);
                ldsm4(ah[mi][0], ah[mi][1], ah[mi][2], ah[mi][3], aB + off);
                if (np3) ldsm4(al[mi][0], al[mi][1], al[mi][2], al[mi][3], aB + 16384 + off);
            }
            #pragma unroll
            for (int g = 0; g < 2; g++) {
                uint32_t off = swz((uint32_t)((wn * 32 + g * 16 + (lane & 15)) * 128) + kcol);
                uint32_t r0, r1, r2, r3;
                ldsm4(r0, r1, r2, r3, bB + off);
                bh[g*2][0] = r0; bh[g*2][1] = r2; bh[g*2+1][0] = r1; bh[g*2+1][1] = r3;
                if (np3) {
                    ldsm4(r0, r1, r2, r3, bB + 16384 + off);
                    bl[g*2][0] = r0; bl[g*2][1] = r2; bl[g*2+1][0] = r1; bl[g*2+1][1] = r3;
                }
            }
            #pragma unroll
            for (int mi = 0; mi < 4; mi++)
                #pragma unroll
                for (int nf = 0; nf < 4; nf++) {
                    mma16816(acc[mi][nf], ah[mi], bh[nf]);
                    if (np3) {
                        mma16816(acc[mi][nf], ah[mi], bl[nf]);
                        mma16816(acc[mi][nf], al[mi], bh[nf]);
                    }
                }
        }
    };

    ldgA(0); cpW(0, 0); stsA(0);
    CP_WAIT0(); __syncthreads();
    for (int c = 0; c < 16; c++) {
        int stg = c & 1;
        if (c < 15) { ldgA(c + 1); cpW(c + 1, stg ^ 1); }
        compute(stg);
        if (c < 15) { stsA(stg ^ 1); CP_WAIT0(); __syncthreads(); }
    }

    const float n0 = nw[0]*0.25f, n1 = nw[1]*0.25f, n2 = nw[2]*0.25f, n3 = nw[3]*0.25f;
    const int gid = lane >> 2, tig = lane & 3;
    #pragma unroll
    for (int mi = 0; mi < 4; mi++) {
        const int row = bm + wm * 64 + mi * 16 + gid;
        #pragma unroll
        for (int nf = 0; nf < 4; nf++) {
            const int col = bn + wn * 32 + nf * 8 + tig * 2;
            float2 bb = *(const float2*)(bias + col);
            float v0 = mtn_f(acc[mi][nf][0] + bb.x, n0, n1, n2, n3);
            float v1 = mtn_f(acc[mi][nf][1] + bb.y, n0, n1, n2, n3);
            float v2 = mtn_f(acc[mi][nf][2] + bb.x, n0, n1, n2, n3);
            float v3 = mtn_f(acc[mi][nf][3] + bb.y, n0, n1, n2, n3);
            *(float2*)(C + (size_t)row * D_ + col) = make_float2(v0, v1);
            *(float2*)(C + (size_t)(row + 8) * D_ + col) = make_float2(v2, v3);
        }
    }
}

// ---------------------------------------------------------------------------
// Scores (HMMA, 3-pass): attn[z,sq,sk] = (q.k) * 0.125/(temp+1e-8)
// Block 128x128, K=64 single chunk. grid (8 sk, 8 sq, 64 z).
// dyn smem: Ah|Al|Bh|Bl 16K each + 1K
// ---------------------------------------------------------------------------
__global__ __launch_bounds__(256) void scores_hmma(
    const float* __restrict__ Q, const float* __restrict__ K,
    const float* __restrict__ temp, float* __restrict__ attn)
{
    extern __shared__ char sraw[];
    const uint32_t sb0 = smem_u32(sraw);
    const uint32_t sbase = (sb0 + 1023) & ~1023u;
    char* sm = sraw + (sbase - sb0);
    const int tid = threadIdx.x, lane = tid & 31, wid = tid >> 5;
    const int wm = wid >> 2, wn = wid & 3;
    const int z = blockIdx.z, b = z >> 4, h = z & 15;
    const int sq0 = blockIdx.y * 128, sk0 = blockIdx.x * 128;

    #pragma unroll
    for (int i = 0; i < 8; i++) {
        int idx = tid + i * 256, r = idx >> 4, c4 = (idx & 15) * 4;
        float4 qv = *(const float4*)(Q + (size_t)(b * S_ + sq0 + r) * D_ + h * HD_ + c4);
        float4 kv = *(const float4*)(K + (size_t)(b * S_ + sk0 + r) * D_ + h * HD_ + c4);
        uint32_t h0, l0, h1, l1;
        uint32_t off = swz((uint32_t)(r * 128 + c4 * 2));
        split2(qv.x, qv.y, h0, l0); split2(qv.z, qv.w, h1, l1);
        *(uint2*)(sm + off) = make_uint2(h0, h1);
        *(uint2*)(sm + 16384 + off) = make_uint2(l0, l1);
        split2(kv.x, kv.y, h0, l0); split2(kv.z, kv.w, h1, l1);
        *(uint2*)(sm + 32768 + off) = make_uint2(h0, h1);
        *(uint2*)(sm + 49152 + off) = make_uint2(l0, l1);
    }
    __syncthreads();

    float acc[4][4][4];
    #pragma unroll
    for (int i = 0; i < 4; i++)
        #pragma unroll
        for (int j = 0; j < 4; j++)
            #pragma unroll
            for (int t = 0; t < 4; t++) acc[i][j][t] = 0.f;

    const uint32_t aB = sbase, bB = sbase + 32768;
    #pragma unroll
    for (int ks = 0; ks < 4; ks++) {
        const uint32_t kcol = (uint32_t)((ks * 16 + ((lane >> 4) << 3)) * 2);
        uint32_t ah[4][4], al[4][4], bh[4][2], bl[4][2];
        #pragma unroll
        for (int mi = 0; mi < 4; mi++) {
            uint32_t off = swz((uint32_t)((wm * 64 + mi * 16 + (lane & 15)) * 128) + kcol);
            ldsm4(ah[mi][0], ah[mi][1], ah[mi][2], ah[mi][3], aB + off);
            ldsm4(al[mi][0], al[mi][1], al[mi][2], al[mi][3], aB + 16384 + off);
        }
        #pragma unroll
        for (int g = 0; g < 2; g++) {
            uint32_t off = swz((uint32_t)((wn * 32 + g * 16 + (lane & 15)) * 128) + kcol);
            uint32_t r0, r1, r2, r3;
            ldsm4(r0, r1, r2, r3, bB + off);
            bh[g*2][0] = r0; bh[g*2][1] = r2; bh[g*2+1][0] = r1; bh[g*2+1][1] = r3;
            ldsm4(r0, r1, r2, r3, bB + 16384 + off);
            bl[g*2][0] = r0; bl[g*2][1] = r2; bl[g*2+1][0] = r1; bl[g*2+1][1] = r3;
        }
        #pragma unroll
        for (int mi = 0; mi < 4; mi++)
            #pragma unroll
            for (int nf = 0; nf < 4; nf++) {
                mma16816(acc[mi][nf], ah[mi], bh[nf]);
                mma16816(acc[mi][nf], ah[mi], bl[nf]);
                mma16816(acc[mi][nf], al[mi], bh[nf]);
            }
    }

    const float f = 0.125f / (temp[0] + 1e-8f);
    const int gid = lane >> 2, tig = lane & 3;
    #pragma unroll
    for (int mi = 0; mi < 4; mi++) {
        const int row = sq0 + wm * 64 + mi * 16 + gid;
        float* rp0 = attn + ((size_t)z * S_ + row) * S_;
        float* rp1 = rp0 + 8 * S_;
        #pragma unroll
        for (int nf = 0; nf < 4; nf++) {
            const int col = sk0 + wn * 32 + nf * 8 + tig * 2;
            *(float2*)(rp0 + col) = make_float2(acc[mi][nf][0] * f, acc[mi][nf][1] * f);
            *(float2*)(rp1 + col) = make_float2(acc[mi][nf][2] * f, acc[mi][nf][3] * f);
        }
    }
}

// ---------------------------------------------------------------------------
// attn @ V (HMMA, 1-pass bf16): out[b,sq,h*64+n]
// Block 128(m) x 64(n), warps 4x2 (32x32), K chunks of 64, double-buffered.
// dyn smem: 2 stages x (Ah 16K | Bh 8K) + 1K
// ---------------------------------------------------------------------------
__global__ __launch_bounds__(256) void attnv_hmma(
    const float* __restrict__ attn, const float* __restrict__ V, float* __restrict__ out)
{
    extern __shared__ char sraw[];
    const uint32_t sb0 = smem_u32(sraw);
    const uint32_t sbase = (sb0 + 1023) & ~1023u;
    char* sm = sraw + (sbase - sb0);
    const int tid = threadIdx.x, lane = tid & 31, wid = tid >> 5;
    const int wm = wid >> 1, wn = wid & 1;
    const int z = blockIdx.y, b = z >> 4, h = z & 15;
    const int sq0 = blockIdx.x * 128;

    float acc[2][4][4];
    #pragma unroll
    for (int i = 0; i < 2; i++)
        #pragma unroll
        for (int j = 0; j < 4; j++)
            #pragma unroll
            for (int t = 0; t < 4; t++) acc[i][j][t] = 0.f;

    float4 av[8], vv[4];

    auto ldg = [&](int c) {
        #pragma unroll
        for (int i = 0; i < 8; i++) {
            int idx = tid + i * 256, r = idx >> 4, c4 = (idx & 15) * 4;
            av[i] = *(const float4*)(attn + ((size_t)z * S_ + sq0 + r) * S_ + c * 64 + c4);
        }
        #pragma unroll
        for (int i = 0; i < 4; i++) {
            int idx = tid + i * 256, r = idx >> 4, c4 = (idx & 15) * 4;
            vv[i] = *(const float4*)(V + (size_t)(b * S_ + c * 64 + r) * D_ + h * HD_ + c4);
        }
    };
    auto sts = [&](int stg) {
        char* dst = sm + stg * 24576;
        #pragma unroll
        for (int i = 0; i < 8; i++) {
            int idx = tid + i * 256, r = idx >> 4, c4 = (idx & 15) * 4;
            uint32_t off = swz((uint32_t)(r * 128 + c4 * 2));
            *(uint2*)(dst + off) = make_uint2(pack_hi(av[i].x, av[i].y), pack_hi(av[i].z, av[i].w));
        }
        #pragma unroll
        for (int i = 0; i < 4; i++) {
            int idx = tid + i * 256, r = idx >> 4, c4 = (idx & 15) * 4;
            uint32_t off = swz((uint32_t)(r * 128 + c4 * 2));
            *(uint2*)(dst + 16384 + off) = make_uint2(pack_hi(vv[i].x, vv[i].y), pack_hi(vv[i].z, vv[i].w));
        }
    };
    auto compute = [&](int stg) {
        uint32_t aB = sbase + stg * 24576;
        uint32_t bB = aB + 16384;
        #pragma unroll
        for (int ks = 0; ks < 4; ks++) {
            const int kb = ks * 16;
            const uint32_t kcol = (uint32_t)((kb + ((lane >> 4) << 3)) * 2);
            uint32_t ah[2][4], bh[4][2];
            #pragma unroll
            for (int mi = 0; mi < 2; mi++) {
                uint32_t off = swz((uint32_t)((wm * 32 + mi * 16 + (lane & 15)) * 128) + kcol);
                ldsm4(ah[mi][0], ah[mi][1], ah[mi][2], ah[mi][3], aB + off);
            }
            #pragma unroll
            for (int g = 0; g < 2; g++) {
                uint32_t off = swz((uint32_t)((kb + (lane & 15)) * 128
                                 + (wn * 32 + g * 16 + ((lane >> 4) << 3)) * 2));
                uint32_t r0, r1, r2, r3;
                ldsm4t(r0, r1, r2, r3, bB + off);
                bh[g*2][0] = r0; bh[g*2][1] = r1; bh[g*2+1][0] = r2; bh[g*2+1][1] = r3;
            }
            #pragma unroll
            for (int mi = 0; mi < 2; mi++)
                #pragma unroll
                for (int nf = 0; nf < 4; nf++)
                    mma16816(acc[mi][nf], ah[mi], bh[nf]);
        }
    };

    ldg(0); sts(0);
    __syncthreads();
    for (int c = 0; c < 16; c++) {
        int stg = c & 1;
        if (c < 15) ldg(c + 1);
        compute(stg);
        if (c < 15) { sts(stg ^ 1); __syncthreads(); }
        else break;
        __syncthreads();
    }

    const int gid = lane >> 2, tig = lane & 3;
    #pragma unroll
    for (int mi = 0; mi < 2; mi++) {
        const int row = sq0 + wm * 32 + mi * 16 + gid;
        #pragma unroll
        for (int nf = 0; nf < 4; nf++) {
            const int col = h * HD_ + wn * 32 + nf * 8 + tig * 2;
            *(float2*)(out + (size_t)(b * S_ + row) * D_ + col) = make_float2(acc[mi][nf][0], acc[mi][nf][1]);
            *(float2*)(out + (size_t)(b * S_ + row + 8) * D_ + col) = make_float2(acc[mi][nf][2], acc[mi][nf][3]);
        }
    }
}

// ---------------------------------------------------------------------------
// Prep: weight split fp32 -> bf16 hi/lo
// ---------------------------------------------------------------------------
__global__ __launch_bounds__(256) void split_w(
    const float4* __restrict__ W, __nv_bfloat162* __restrict__ Wh, __nv_bfloat162* __restrict__ Wl)
{
    int i = blockIdx.x * 256 + threadIdx.x;
    float4 v = W[i];
    __nv_bfloat16 hx = __float2bfloat16(v.x), hy = __float2bfloat16(v.y);
    __nv_bfloat16 hz = __float2bfloat16(v.z), hw = __float2bfloat16(v.w);
    __nv_bfloat16 lx = __float2bfloat16(v.x - __bfloat162float(hx));
    __nv_bfloat16 ly = __float2bfloat16(v.y - __bfloat162float(hy));
    __nv_bfloat16 lz = __float2bfloat16(v.z - __bfloat162float(hz));
    __nv_bfloat16 lw = __float2bfloat16(v.w - __bfloat162float(hw));
    Wh[i*2]   = __halves2bfloat162(hx, hy);
    Wh[i*2+1] = __halves2bfloat162(hz, hw);
    Wl[i*2]   = __halves2bfloat162(lx, ly);
    Wl[i*2+1] = __halves2bfloat162(lz, lw);
}

__global__ __launch_bounds__(256) void transp1024(const float* __restrict__ A, float* __restrict__ At)
{
    __shared__ float t[32][33];
    int x = blockIdx.x * 32 + threadIdx.x;
    int y0 = blockIdx.y * 32 + threadIdx.y;
    #pragma unroll
    for (int r = 0; r < 4; r++)
        t[threadIdx.y + r*8][threadIdx.x] = A[(size_t)(y0 + r*8) * D_ + x];
    __syncthreads();
    int x2 = blockIdx.y * 32 + threadIdx.x;
    int y2 = blockIdx.x * 32 + threadIdx.y;
    #pragma unroll
    for (int r = 0; r < 4; r++)
        At[(size_t)(y2 + r*8) * D_ + x2] = t[threadIdx.x][threadIdx.y + r*8];
}

// ---------------------------------------------------------------------------
// ECM compensation (sparse, in place), coalesced via transposed Wc
// ---------------------------------------------------------------------------
__global__ __launch_bounds__(256) void comp_inplace(
    float* __restrict__ X, const float* __restrict__ WcT, const float* __restrict__ bc)
{
    __shared__ float row[1024];
    __shared__ int   nzi[1024];
    __shared__ float nzv[1024];
    __shared__ int   cnt;
    const int tid = threadIdx.x;
    float* xr = X + (size_t)blockIdx.x * D_;
    if (tid == 0) cnt = 0;
    __syncthreads();
    for (int j = tid; j < D_; j += 256) {
        float v = xr[j];
        row[j] = v;
        if (v != 0.f) { int p = atomicAdd(&cnt, 1); nzi[p] = j; nzv[p] = v; }
    }
    __syncthreads();
    const int c = cnt;
    for (int n = tid; n < D_; n += 256) {
        float acc = row[n] + bc[n];
        for (int t = 0; t < c; t++)
            acc = fmaf(-nzv[t], WcT[(size_t)nzi[t] * D_ + n], acc);
        xr[n] = acc;
    }
}

// ---------------------------------------------------------------------------
// Row softmax, in place
// ---------------------------------------------------------------------------
__global__ __launch_bounds__(256) void softmax_kernel(float* __restrict__ attn)
{
    __shared__ float red[8];
    const int tid = threadIdx.x;
    float* p = attn + (size_t)blockIdx.x * 1024;
    float v[4];
    #pragma unroll
    for (int i = 0; i < 4; i++) v[i] = p[tid + i*256];
    float m = fmaxf(fmaxf(v[0], v[1]), fmaxf(v[2], v[3]));
    #pragma unroll
    for (int o = 16; o > 0; o >>= 1) m = fmaxf(m, __shfl_xor_sync(0xffffffffu, m, o));
    if ((tid & 31) == 0) red[tid >> 5] = m;
    __syncthreads();
    m = red[0];
    #pragma unroll
    for (int i = 1; i < 8; i++) m = fmaxf(m, red[i]);
    float e[4]; float s = 0.f;
    #pragma unroll
    for (int i = 0; i < 4; i++) { e[i] = expf(v[i] - m); s += e[i]; }
    #pragma unroll
    for (int o = 16; o > 0; o >>= 1) s += __shfl_xor_sync(0xffffffffu, s, o);
    __syncthreads();
    if ((tid & 31) == 0) red[tid >> 5] = s;
    __syncthreads();
    s = 0.f;
    #pragma unroll
    for (int i = 0; i < 8; i++) s += red[i];
    #pragma unroll
    for (int i = 0; i < 4; i++) p[tid + i*256] = e[i] / s;
}

// ---------------------------------------------------------------------------
// Launch
// ---------------------------------------------------------------------------
extern "C" void kernel_launch(void* const* d_in, const int* in_sizes, int n_in,
                              void* d_out, int out_size)
{
    const float* query = (const float*)d_in[0];
    const float* key   = (const float*)d_in[1];
    const float* value = (const float*)d_in[2];
    const float* Wq  = (const float*)d_in[3];
    const float* bq  = (const float*)d_in[4];
    const float* Wk  = (const float*)d_in[5];
    const float* bk  = (const float*)d_in[6];
    const float* Wv  = (const float*)d_in[7];
    const float* bv  = (const float*)d_in[8];
    const float* Wo  = (const float*)d_in[9];
    const float* bo  = (const float*)d_in[10];
    const float* Wqc = (const float*)d_in[11];
    const float* bqc = (const float*)d_in[12];
    const float* Wkc = (const float*)d_in[13];
    const float* bkc = (const float*)d_in[14];
    const float* Wvc = (const float*)d_in[15];
    const float* bvc = (const float*)d_in[16];
    const float* nw_q = (const float*)d_in[17];
    const float* nw_k = (const float*)d_in[18];
    const float* nw_v = (const float*)d_in[19];
    const float* nw_o = (const float*)d_in[20];
    const float* temperature = (const float*)d_in[21];

    float *q, *k, *v, *ao, *attn_fb, *out_fb, *wct;
    __nv_bfloat16 *wh, *wl;
    cudaGetSymbolAddress((void**)&q,  g_q);
    cudaGetSymbolAddress((void**)&k,  g_k);
    cudaGetSymbolAddress((void**)&v,  g_v);
    cudaGetSymbolAddress((void**)&ao, g_ao);
    cudaGetSymbolAddress((void**)&attn_fb, g_attn_fb);
    cudaGetSymbolAddress((void**)&out_fb,  g_out_fb);
    cudaGetSymbolAddress((void**)&wh, g_Wh);
    cudaGetSymbolAddress((void**)&wl, g_Wl);
    cudaGetSymbolAddress((void**)&wct, g_WcT);

    const size_t NOUT = (size_t)MTOT * D_;
    const size_t NATT = (size_t)B_ * H_ * S_ * S_;
    float* out = (float*)d_out;
    float* out_ptr;
    float* attn_ptr;
    const size_t osz = (size_t)out_size;
    if (osz == NOUT + NATT)      { out_ptr = out;    attn_ptr = out + NOUT; }
    else if (osz == NOUT)        { out_ptr = out;    attn_ptr = attn_fb;    }
    else if (osz == NATT)        { out_ptr = out_fb; attn_ptr = out;        }
    else                         { out_ptr = out;    attn_ptr = out + NOUT; }

    const int SMEM_PROJ  = 2*65536 + 1024;
    const int SMEM_SCORE = 65536 + 1024;
    const int SMEM_AV    = 2*24576 + 1024;
    cudaFuncSetAttribute(proj_hmma,   cudaFuncAttributeMaxDynamicSharedMemorySize, SMEM_PROJ);
    cudaFuncSetAttribute(scores_hmma, cudaFuncAttributeMaxDynamicSharedMemorySize, SMEM_SCORE);
    cudaFuncSetAttribute(attnv_hmma,  cudaFuncAttributeMaxDynamicSharedMemorySize, SMEM_AV);

    const size_t WSZ = (size_t)D_ * D_;

    split_w<<<1024, 256>>>((const float4*)Wq, (__nv_bfloat162*)(wh),          (__nv_bfloat162*)(wl));
    split_w<<<1024, 256>>>((const float4*)Wk, (__nv_bfloat162*)(wh + WSZ),    (__nv_bfloat162*)(wl + WSZ));
    split_w<<<1024, 256>>>((const float4*)Wv, (__nv_bfloat162*)(wh + 2*WSZ),  (__nv_bfloat162*)(wl + 2*WSZ));
    split_w<<<1024, 256>>>((const float4*)Wo, (__nv_bfloat162*)(wh + 3*WSZ),  (__nv_bfloat162*)(wl + 3*WSZ));
    transp1024<<<dim3(32,32), dim3(32,8)>>>(Wqc, wct);
    transp1024<<<dim3(32,32), dim3(32,8)>>>(Wkc, wct + WSZ);
    transp1024<<<dim3(32,32), dim3(32,8)>>>(Wvc, wct + 2*WSZ);

    dim3 gproj(D_/128, MTOT/128);   // (8, 32)

    proj_hmma<<<gproj, 256, SMEM_PROJ>>>(query, wh,         wl,         bq, nw_q, q, 1);
    proj_hmma<<<gproj, 256, SMEM_PROJ>>>(key,   wh + WSZ,   wl + WSZ,   bk, nw_k, k, 1);
    proj_hmma<<<gproj, 256, SMEM_PROJ>>>(value, wh + 2*WSZ, wl + 2*WSZ, bv, nw_v, v, 1);

    comp_inplace<<<MTOT, 256>>>(q, wct,         bqc);
    comp_inplace<<<MTOT, 256>>>(k, wct + WSZ,   bkc);
    comp_inplace<<<MTOT, 256>>>(v, wct + 2*WSZ, bvc);

    scores_hmma<<<dim3(8, 8, B_*H_), 256, SMEM_SCORE>>>(q, k, temperature, attn_ptr);
    softmax_kernel<<<B_*H_*S_, 256>>>(attn_ptr);
    attnv_hmma<<<dim3(8, B_*H_), 256, SMEM_AV>>>(attn_ptr, v, ao);

    proj_hmma<<<gproj, 256, SMEM_PROJ>>>(ao, wh + 3*WSZ, wl + 3*WSZ, bo, nw_o, out_ptr, 0);
}

// round 4
// speedup vs baseline: 2.8651x; 1.1740x over previous
#include <cuda_runtime.h>
#include <cuda_bf16.h>
#include <cstdint>

#define B_  4
#define S_  1024
#define D_  1024
#define H_  16
#define HD_ 64
#define MTOT (B_*S_)        // 4096
#define NZR (64*1024)       // B*H*S rows of attn

// ---------------------------------------------------------------------------
// Static scratch
// ---------------------------------------------------------------------------
__device__ float g_q[MTOT*D_];
__device__ float g_k[MTOT*D_];
__device__ float g_v[MTOT*D_];
__device__ float g_attn_fb[(size_t)B_*H_*S_*S_];
__device__ float g_out_fb[MTOT*D_];
__device__ __nv_bfloat16 g_Wh[(size_t)4*D_*D_];
__device__ __nv_bfloat16 g_Wl[(size_t)4*D_*D_];
__device__ float g_WcT[(size_t)3*D_*D_];
__device__ __nv_bfloat16 g_Ih[(size_t)3*MTOT*D_];   // split inputs hi
__device__ __nv_bfloat16 g_Il[(size_t)3*MTOT*D_];   // split inputs lo
__device__ __nv_bfloat16 g_qh[MTOT*D_], g_ql[MTOT*D_];
__device__ __nv_bfloat16 g_kh[MTOT*D_], g_kl[MTOT*D_];
__device__ __nv_bfloat16 g_vh[MTOT*D_], g_vl[MTOT*D_];
__device__ __nv_bfloat16 g_aoh[MTOT*D_];
__device__ float g_rspart[(size_t)NZR*8];
__device__ float g_rinv[NZR];

// ---------------------------------------------------------------------------
// Helpers
// ---------------------------------------------------------------------------
__device__ __forceinline__ uint32_t smem_u32(const void* p) {
    uint32_t a;
    asm("{ .reg .u64 t; cvta.to.shared.u64 t, %1; cvt.u32.u64 %0, t; }" : "=r"(a) : "l"(p));
    return a;
}
__device__ __forceinline__ uint32_t swz(uint32_t off) { return off ^ ((off >> 3) & 0x70); }

__device__ __forceinline__ void ldsm4(uint32_t& r0, uint32_t& r1, uint32_t& r2, uint32_t& r3, uint32_t a) {
    asm volatile("ldmatrix.sync.aligned.m8n8.x4.shared.b16 {%0,%1,%2,%3}, [%4];"
                 : "=r"(r0), "=r"(r1), "=r"(r2), "=r"(r3) : "r"(a));
}
__device__ __forceinline__ void ldsm4t(uint32_t& r0, uint32_t& r1, uint32_t& r2, uint32_t& r3, uint32_t a) {
    asm volatile("ldmatrix.sync.aligned.m8n8.x4.trans.shared.b16 {%0,%1,%2,%3}, [%4];"
                 : "=r"(r0), "=r"(r1), "=r"(r2), "=r"(r3) : "r"(a));
}
__device__ __forceinline__ void mma16816(float* c, const uint32_t* a, const uint32_t* b) {
    asm volatile("mma.sync.aligned.m16n8k16.row.col.f32.bf16.bf16.f32 "
                 "{%0,%1,%2,%3}, {%4,%5,%6,%7}, {%8,%9}, {%0,%1,%2,%3};"
                 : "+f"(c[0]), "+f"(c[1]), "+f"(c[2]), "+f"(c[3])
                 : "r"(a[0]), "r"(a[1]), "r"(a[2]), "r"(a[3]), "r"(b[0]), "r"(b[1]));
}
__device__ __forceinline__ void cpasync16(uint32_t sdst, const void* g) {
    asm volatile("cp.async.ca.shared.global [%0], [%1], 16;" :: "r"(sdst), "l"(g) : "memory");
}
#define CP_COMMIT() asm volatile("cp.async.commit_group;" ::: "memory")
#define CP_WAIT0()  asm volatile("cp.async.wait_group 0;" ::: "memory")
#define CP_WAIT1()  asm volatile("cp.async.wait_group 1;" ::: "memory")

__device__ __forceinline__ void split2(float x, float y, uint32_t& hi, uint32_t& lo) {
    __nv_bfloat16 hx = __float2bfloat16(x), hy = __float2bfloat16(y);
    __nv_bfloat16 lx = __float2bfloat16(x - __bfloat162float(hx));
    __nv_bfloat16 ly = __float2bfloat16(y - __bfloat162float(hy));
    hi = ((uint32_t)__bfloat16_as_ushort(hy) << 16) | (uint32_t)__bfloat16_as_ushort(hx);
    lo = ((uint32_t)__bfloat16_as_ushort(ly) << 16) | (uint32_t)__bfloat16_as_ushort(lx);
}
__device__ __forceinline__ uint32_t pack_hi(float x, float y) {
    return ((uint32_t)__bfloat16_as_ushort(__float2bfloat16(y)) << 16)
         |  (uint32_t)__bfloat16_as_ushort(__float2bfloat16(x));
}
__device__ __forceinline__ float mtn_f(float x, float n0, float n1, float n2, float n3) {
    float mem = x * 0.5f;
    float s = 0.f;
    if (mem >= 1.f) { s += n0; mem -= 1.f; }
    if (mem >= 2.f) { s += n1; mem -= 2.f; }
    if (mem >= 3.f) { s += n2; mem -= 3.f; }
    if (mem >= 4.f) { s += n3; mem -= 4.f; }
    return s;
}

// ---------------------------------------------------------------------------
// Projection GEMM: C = mtn(A @ W^T + bias). A,W pre-split bf16 hi/lo.
// Block 128x128, 8 warps (2x4), K chunks of 64, cp.async double-buffered.
// np3=1: 3-pass split; np3=0: single hi pass.
// smem: 2 stages x (Ah 16K | Al 16K | Wh 16K | Wl 16K) + 1K align
// ---------------------------------------------------------------------------
__global__ __launch_bounds__(256) void proj_hmma(
    const __nv_bfloat16* __restrict__ Ah, const __nv_bfloat16* __restrict__ Al,
    const __nv_bfloat16* __restrict__ Wh, const __nv_bfloat16* __restrict__ Wl,
    const float* __restrict__ bias, const float* __restrict__ nw,
    float* __restrict__ C, int np3)
{
    extern __shared__ char sraw[];
    const uint32_t sb0 = smem_u32(sraw);
    const uint32_t sbase = (sb0 + 1023) & ~1023u;
    const int tid = threadIdx.x, lane = tid & 31, wid = tid >> 5;
    const int wm = wid >> 2, wn = wid & 3;
    const int bm = blockIdx.y * 128, bn = blockIdx.x * 128;

    float acc[4][4][4];
    #pragma unroll
    for (int i = 0; i < 4; i++)
        #pragma unroll
        for (int j = 0; j < 4; j++)
            #pragma unroll
            for (int t = 0; t < 4; t++) acc[i][j][t] = 0.f;

    auto issue = [&](int c, int stg) {
        uint32_t base = sbase + stg * 65536;
        #pragma unroll
        for (int i = 0; i < 4; i++) {
            int idx = tid + i * 256, r = idx >> 3, c8 = (idx & 7) * 8;
            uint32_t off = swz((uint32_t)(r * 128 + c8 * 2));
            const size_t ga = (size_t)(bm + r) * D_ + c * 64 + c8;
            const size_t gw = (size_t)(bn + r) * D_ + c * 64 + c8;
            cpasync16(base + off, Ah + ga);
            cpasync16(base + 32768 + off, Wh + gw);
            if (np3) {
                cpasync16(base + 16384 + off, Al + ga);
                cpasync16(base + 49152 + off, Wl + gw);
            }
        }
        CP_COMMIT();
    };
    auto compute = [&](int stg) {
        uint32_t aB = sbase + stg * 65536;
        uint32_t bB = aB + 32768;
        #pragma unroll
        for (int ks = 0; ks < 4; ks++) {
            const uint32_t kcol = (uint32_t)((ks * 16 + ((lane >> 4) << 3)) * 2);
            uint32_t ah[4][4], al[4][4], bh[4][2], bl[4][2];
            #pragma unroll
            for (int mi = 0; mi < 4; mi++) {
                uint32_t off = swz((uint32_t)((wm * 64 + mi * 16 + (lane & 15)) * 128) + kcol);
                ldsm4(ah[mi][0], ah[mi][1], ah[mi][2], ah[mi][3], aB + off);
                if (np3) ldsm4(al[mi][0], al[mi][1], al[mi][2], al[mi][3], aB + 16384 + off);
            }
            #pragma unroll
            for (int g = 0; g < 2; g++) {
                uint32_t off = swz((uint32_t)((wn * 32 + g * 16 + (lane & 15)) * 128) + kcol);
                uint32_t r0, r1, r2, r3;
                ldsm4(r0, r1, r2, r3, bB + off);
                bh[g*2][0] = r0; bh[g*2][1] = r2; bh[g*2+1][0] = r1; bh[g*2+1][1] = r3;
                if (np3) {
                    ldsm4(r0, r1, r2, r3, bB + 16384 + off);
                    bl[g*2][0] = r0; bl[g*2][1] = r2; bl[g*2+1][0] = r1; bl[g*2+1][1] = r3;
                }
            }
            #pragma unroll
            for (int mi = 0; mi < 4; mi++)
                #pragma unroll
                for (int nf = 0; nf < 4; nf++) {
                    mma16816(acc[mi][nf], ah[mi], bh[nf]);
                    if (np3) {
                        mma16816(acc[mi][nf], ah[mi], bl[nf]);
                        mma16816(acc[mi][nf], al[mi], bh[nf]);
                    }
                }
        }
    };

    issue(0, 0);
    for (int c = 0; c < 16; c++) {
        const int stg = c & 1;
        if (c < 15) { issue(c + 1, stg ^ 1); CP_WAIT1(); }
        else CP_WAIT0();
        __syncthreads();
        compute(stg);
        __syncthreads();
    }

    const float n0 = nw[0]*0.25f, n1 = nw[1]*0.25f, n2 = nw[2]*0.25f, n3 = nw[3]*0.25f;
    const int gid = lane >> 2, tig = lane & 3;
    #pragma unroll
    for (int mi = 0; mi < 4; mi++) {
        const int row = bm + wm * 64 + mi * 16 + gid;
        #pragma unroll
        for (int nf = 0; nf < 4; nf++) {
            const int col = bn + wn * 32 + nf * 8 + tig * 2;
            float2 bb = *(const float2*)(bias + col);
            float v0 = mtn_f(acc[mi][nf][0] + bb.x, n0, n1, n2, n3);
            float v1 = mtn_f(acc[mi][nf][1] + bb.y, n0, n1, n2, n3);
            float v2 = mtn_f(acc[mi][nf][2] + bb.x, n0, n1, n2, n3);
            float v3 = mtn_f(acc[mi][nf][3] + bb.y, n0, n1, n2, n3);
            *(float2*)(C + (size_t)row * D_ + col) = make_float2(v0, v1);
            *(float2*)(C + (size_t)(row + 8) * D_ + col) = make_float2(v2, v3);
        }
    }
}

// ---------------------------------------------------------------------------
// Scores + exp + partial row sums. e = exp(score * 0.125/(temp+1e-8)).
// Block 128x128, K=64 single shot (3-pass). grid (8 sk, 8 sq, 64 z).
// smem: qh|ql|kh|kl 16K each + spart 2K + 1K align
// ---------------------------------------------------------------------------
__global__ __launch_bounds__(256) void scores_hmma(
    const __nv_bfloat16* __restrict__ Qh, const __nv_bfloat16* __restrict__ Ql,
    const __nv_bfloat16* __restrict__ Kh, const __nv_bfloat16* __restrict__ Kl,
    const float* __restrict__ temp, float* __restrict__ attn)
{
    extern __shared__ char sraw[];
    const uint32_t sb0 = smem_u32(sraw);
    const uint32_t sbase = (sb0 + 1023) & ~1023u;
    char* sm = sraw + (sbase - sb0);
    const int tid = threadIdx.x, lane = tid & 31, wid = tid >> 5;
    const int wm = wid >> 2, wn = wid & 3;
    const int z = blockIdx.z, b = z >> 4, h = z & 15;
    const int sq0 = blockIdx.y * 128, sk0 = blockIdx.x * 128;

    #pragma unroll
    for (int i = 0; i < 4; i++) {
        int idx = tid + i * 256, r = idx >> 3, c8 = (idx & 7) * 8;
        uint32_t off = swz((uint32_t)(r * 128 + c8 * 2));
        const size_t gq = (size_t)(b * S_ + sq0 + r) * D_ + h * HD_ + c8;
        const size_t gk = (size_t)(b * S_ + sk0 + r) * D_ + h * HD_ + c8;
        cpasync16(sbase + off, Qh + gq);
        cpasync16(sbase + 16384 + off, Ql + gq);
        cpasync16(sbase + 32768 + off, Kh + gk);
        cpasync16(sbase + 49152 + off, Kl + gk);
    }
    CP_COMMIT(); CP_WAIT0();
    __syncthreads();

    float acc[4][4][4];
    #pragma unroll
    for (int i = 0; i < 4; i++)
        #pragma unroll
        for (int j = 0; j < 4; j++)
            #pragma unroll
            for (int t = 0; t < 4; t++) acc[i][j][t] = 0.f;

    const uint32_t aB = sbase, bB = sbase + 32768;
    #pragma unroll
    for (int ks = 0; ks < 4; ks++) {
        const uint32_t kcol = (uint32_t)((ks * 16 + ((lane >> 4) << 3)) * 2);
        uint32_t ah[4][4], al[4][4], bh[4][2], bl[4][2];
        #pragma unroll
        for (int mi = 0; mi < 4; mi++) {
            uint32_t off = swz((uint32_t)((wm * 64 + mi * 16 + (lane & 15)) * 128) + kcol);
            ldsm4(ah[mi][0], ah[mi][1], ah[mi][2], ah[mi][3], aB + off);
            ldsm4(al[mi][0], al[mi][1], al[mi][2], al[mi][3], aB + 16384 + off);
        }
        #pragma unroll
        for (int g = 0; g < 2; g++) {
            uint32_t off = swz((uint32_t)((wn * 32 + g * 16 + (lane & 15)) * 128) + kcol);
            uint32_t r0, r1, r2, r3;
            ldsm4(r0, r1, r2, r3, bB + off);
            bh[g*2][0] = r0; bh[g*2][1] = r2; bh[g*2+1][0] = r1; bh[g*2+1][1] = r3;
            ldsm4(r0, r1, r2, r3, bB + 16384 + off);
            bl[g*2][0] = r0; bl[g*2][1] = r2; bl[g*2+1][0] = r1; bl[g*2+1][1] = r3;
        }
        #pragma unroll
        for (int mi = 0; mi < 4; mi++)
            #pragma unroll
            for (int nf = 0; nf < 4; nf++) {
                mma16816(acc[mi][nf], ah[mi], bh[nf]);
                mma16816(acc[mi][nf], ah[mi], bl[nf]);
                mma16816(acc[mi][nf], al[mi], bh[nf]);
            }
    }

    const float f = 0.125f / (temp[0] + 1e-8f);
    const int gid = lane >> 2, tig = lane & 3;
    float* spart = (float*)(sm + 65536);   // [4][128]
    #pragma unroll
    for (int mi = 0; mi < 4; mi++) {
        const int row = sq0 + wm * 64 + mi * 16 + gid;
        float* rp0 = attn + ((size_t)z * S_ + row) * S_;
        float* rp1 = rp0 + 8 * S_;
        float s0 = 0.f, s1 = 0.f;
        #pragma unroll
        for (int nf = 0; nf < 4; nf++) {
            const int col = sk0 + wn * 32 + nf * 8 + tig * 2;
            float e0 = expf(acc[mi][nf][0] * f);
            float e1 = expf(acc[mi][nf][1] * f);
            float e2 = expf(acc[mi][nf][2] * f);
            float e3 = expf(acc[mi][nf][3] * f);
            *(float2*)(rp0 + col) = make_float2(e0, e1);
            *(float2*)(rp1 + col) = make_float2(e2, e3);
            s0 += e0 + e1; s1 += e2 + e3;
        }
        s0 += __shfl_xor_sync(0xffffffffu, s0, 1);
        s0 += __shfl_xor_sync(0xffffffffu, s0, 2);
        s1 += __shfl_xor_sync(0xffffffffu, s1, 1);
        s1 += __shfl_xor_sync(0xffffffffu, s1, 2);
        if (tig == 0) {
            spart[wn * 128 + wm * 64 + mi * 16 + gid]     = s0;
            spart[wn * 128 + wm * 64 + mi * 16 + gid + 8] = s1;
        }
    }
    __syncthreads();
    if (tid < 128) {
        float s = (spart[tid] + spart[128 + tid]) + (spart[256 + tid] + spart[384 + tid]);
        g_rspart[((size_t)z * S_ + sq0 + tid) * 8 + blockIdx.x] = s;
    }
}

// ---------------------------------------------------------------------------
// rinv[row] = 1 / sum_k rspart[row][k]  (deterministic fixed-order sum)
// ---------------------------------------------------------------------------
__global__ __launch_bounds__(256) void finalize_rinv()
{
    int row = blockIdx.x * 256 + threadIdx.x;
    const float4* p = (const float4*)(g_rspart + (size_t)row * 8);
    float4 a = p[0], bv = p[1];
    float s = ((a.x + a.y) + (a.z + a.w)) + ((bv.x + bv.y) + (bv.z + bv.w));
    g_rinv[row] = 1.f / s;
}

// ---------------------------------------------------------------------------
// attnv: normalize e -> w (write back to attn), compute out = w @ V (bf16 hi)
// Block 128(m) x 64(n), warps 4x2, K chunks 64, V via cp.async.
// smem: 2 stages x (A 16K | V 8K) + 1K align
// ---------------------------------------------------------------------------
__global__ __launch_bounds__(256) void attnv_hmma(
    float* __restrict__ attn, const __nv_bfloat16* __restrict__ Vh,
    __nv_bfloat16* __restrict__ aoh)
{
    extern __shared__ char sraw[];
    const uint32_t sb0 = smem_u32(sraw);
    const uint32_t sbase = (sb0 + 1023) & ~1023u;
    char* sm = sraw + (sbase - sb0);
    const int tid = threadIdx.x, lane = tid & 31, wid = tid >> 5;
    const int wm = wid >> 1, wn = wid & 1;
    const int z = blockIdx.y, b = z >> 4, h = z & 15;
    const int sq0 = blockIdx.x * 128;

    float acc[2][4][4];
    #pragma unroll
    for (int i = 0; i < 2; i++)
        #pragma unroll
        for (int j = 0; j < 4; j++)
            #pragma unroll
            for (int t = 0; t < 4; t++) acc[i][j][t] = 0.f;

    float rinv8[8];
    #pragma unroll
    for (int i = 0; i < 8; i++)
        rinv8[i] = g_rinv[(size_t)z * S_ + sq0 + (tid >> 4) + i * 16];

    float4 av[8];
    auto ldgA = [&](int c) {
        #pragma unroll
        for (int i = 0; i < 8; i++) {
            int r = (tid >> 4) + i * 16, c4 = (tid & 15) * 4;
            float* p = attn + ((size_t)z * S_ + sq0 + r) * S_ + c * 64 + c4;
            float4 v = *(const float4*)p;
            v.x *= rinv8[i]; v.y *= rinv8[i]; v.z *= rinv8[i]; v.w *= rinv8[i];
            *(float4*)p = v;   // final normalized attention weights
            av[i] = v;
        }
    };
    auto cpV = [&](int c, int stg) {
        uint32_t base = sbase + stg * 24576 + 16384;
        #pragma unroll
        for (int i = 0; i < 2; i++) {
            int idx = tid + i * 256, r = idx >> 3, c8 = (idx & 7) * 8;
            uint32_t off = swz((uint32_t)(r * 128 + c8 * 2));
            cpasync16(base + off, Vh + (size_t)(b * S_ + c * 64 + r) * D_ + h * HD_ + c8);
        }
        CP_COMMIT();
    };
    auto stsA = [&](int stg) {
        char* dst = sm + stg * 24576;
        #pragma unroll
        for (int i = 0; i < 8; i++) {
            int r = (tid >> 4) + i * 16, c4 = (tid & 15) * 4;
            uint32_t off = swz((uint32_t)(r * 128 + c4 * 2));
            *(uint2*)(dst + off) = make_uint2(pack_hi(av[i].x, av[i].y), pack_hi(av[i].z, av[i].w));
        }
    };
    auto compute = [&](int stg) {
        uint32_t aB = sbase + stg * 24576;
        uint32_t bB = aB + 16384;
        #pragma unroll
        for (int ks = 0; ks < 4; ks++) {
            const int kb = ks * 16;
            const uint32_t kcol = (uint32_t)((kb + ((lane >> 4) << 3)) * 2);
            uint32_t ah[2][4], bh[4][2];
            #pragma unroll
            for (int mi = 0; mi < 2; mi++) {
                uint32_t off = swz((uint32_t)((wm * 32 + mi * 16 + (lane & 15)) * 128) + kcol);
                ldsm4(ah[mi][0], ah[mi][1], ah[mi][2], ah[mi][3], aB + off);
            }
            #pragma unroll
            for (int g = 0; g < 2; g++) {
                uint32_t off = swz((uint32_t)((kb + (lane & 15)) * 128
                                 + (wn * 32 + g * 16 + ((lane >> 4) << 3)) * 2));
                uint32_t r0, r1, r2, r3;
                ldsm4t(r0, r1, r2, r3, bB + off);
                bh[g*2][0] = r0; bh[g*2][1] = r1; bh[g*2+1][0] = r2; bh[g*2+1][1] = r3;
            }
            #pragma unroll
            for (int mi = 0; mi < 2; mi++)
                #pragma unroll
                for (int nf = 0; nf < 4; nf++)
                    mma16816(acc[mi][nf], ah[mi], bh[nf]);
        }
    };

    ldgA(0); cpV(0, 0);
    stsA(0);
    CP_WAIT0(); __syncthreads();
    for (int c = 0; c < 16; c++) {
        const int stg = c & 1;
        if (c < 15) { ldgA(c + 1); cpV(c + 1, stg ^ 1); }
        compute(stg);
        if (c < 15) {
            stsA(stg ^ 1);
            CP_WAIT0(); __syncthreads();
        }
    }

    const int gid = lane >> 2, tig = lane & 3;
    #pragma unroll
    for (int mi = 0; mi < 2; mi++) {
        const int row = sq0 + wm * 32 + mi * 16 + gid;
        #pragma unroll
        for (int nf = 0; nf < 4; nf++) {
            const int col = h * HD_ + wn * 32 + nf * 8 + tig * 2;
            *(uint32_t*)(aoh + (size_t)(b * S_ + row) * D_ + col) = pack_hi(acc[mi][nf][0], acc[mi][nf][1]);
            *(uint32_t*)(aoh + (size_t)(b * S_ + row + 8) * D_ + col) = pack_hi(acc[mi][nf][2], acc[mi][nf][3]);
        }
    }
}

// ---------------------------------------------------------------------------
// Prep kernels
// ---------------------------------------------------------------------------
__global__ __launch_bounds__(256) void split_w4(
    const float4* __restrict__ W0, const float4* __restrict__ W1,
    const float4* __restrict__ W2, const float4* __restrict__ W3,
    __nv_bfloat16* __restrict__ Wh, __nv_bfloat16* __restrict__ Wl)
{
    const int t = blockIdx.y;
    const float4* W = (t == 0) ? W0 : (t == 1) ? W1 : (t == 2) ? W2 : W3;
    const size_t i = (size_t)blockIdx.x * 256 + threadIdx.x;   // over 262144 float4
    float4 v = W[i];
    uint32_t h0, l0, h1, l1;
    split2(v.x, v.y, h0, l0);
    split2(v.z, v.w, h1, l1);
    const size_t o = (size_t)t * D_ * D_ / 4 + i;
    ((uint2*)Wh)[o] = make_uint2(h0, h1);
    ((uint2*)Wl)[o] = make_uint2(l0, l1);
}

__global__ __launch_bounds__(256) void split_act(
    const float4* __restrict__ s0, const float4* __restrict__ s1, const float4* __restrict__ s2)
{
    const int t = blockIdx.y;
    const float4* src = (t == 0) ? s0 : (t == 1) ? s1 : s2;
    const size_t i = (size_t)blockIdx.x * 256 + threadIdx.x;   // over 1M float4
    float4 v = src[i];
    uint32_t h0, l0, h1, l1;
    split2(v.x, v.y, h0, l0);
    split2(v.z, v.w, h1, l1);
    const size_t o = (size_t)t * MTOT * D_ / 4 + i;
    ((uint2*)g_Ih)[o] = make_uint2(h0, h1);
    ((uint2*)g_Il)[o] = make_uint2(l0, l1);
}

__global__ __launch_bounds__(256) void transp3(
    const float* __restrict__ A0, const float* __restrict__ A1, const float* __restrict__ A2)
{
    __shared__ float t[32][33];
    const int sel = blockIdx.z;
    const float* A = (sel == 0) ? A0 : (sel == 1) ? A1 : A2;
    float* At = g_WcT + (size_t)sel * D_ * D_;
    int x = blockIdx.x * 32 + threadIdx.x;
    int y0 = blockIdx.y * 32 + threadIdx.y;
    #pragma unroll
    for (int r = 0; r < 4; r++)
        t[threadIdx.y + r*8][threadIdx.x] = A[(size_t)(y0 + r*8) * D_ + x];
    __syncthreads();
    int x2 = blockIdx.y * 32 + threadIdx.x;
    int y2 = blockIdx.x * 32 + threadIdx.y;
    #pragma unroll
    for (int r = 0; r < 4; r++)
        At[(size_t)(y2 + r*8) * D_ + x2] = t[threadIdx.x][threadIdx.y + r*8];
}

// ---------------------------------------------------------------------------
// ECM compensation: out = x + bc - spikes @ WcT  (sparse), writes bf16 hi/lo
// ---------------------------------------------------------------------------
__global__ __launch_bounds__(256) void comp_bf16(
    const float* __restrict__ X, const float* __restrict__ WcT, const float* __restrict__ bc,
    __nv_bfloat16* __restrict__ Oh, __nv_bfloat16* __restrict__ Ol)
{
    __shared__ float row[1024];
    __shared__ int   nzi[1024];
    __shared__ float nzv[1024];
    __shared__ int   cnt;
    const int tid = threadIdx.x;
    const float* xr = X + (size_t)blockIdx.x * D_;
    if (tid == 0) cnt = 0;
    __syncthreads();
    for (int j = tid; j < D_; j += 256) {
        float v = xr[j];
        row[j] = v;
        if (v != 0.f) { int p = atomicAdd(&cnt, 1); nzi[p] = j; nzv[p] = v; }
    }
    __syncthreads();
    const int c = cnt;
    const size_t base = (size_t)blockIdx.x * D_;
    for (int n = tid; n < D_; n += 256) {
        float acc = row[n] + bc[n];
        for (int t = 0; t < c; t++)
            acc = fmaf(-nzv[t], WcT[(size_t)nzi[t] * D_ + n], acc);
        __nv_bfloat16 hh = __float2bfloat16(acc);
        Oh[base + n] = hh;
        Ol[base + n] = __float2bfloat16(acc - __bfloat162float(hh));
    }
}

// ---------------------------------------------------------------------------
// Launch
// ---------------------------------------------------------------------------
extern "C" void kernel_launch(void* const* d_in, const int* in_sizes, int n_in,
                              void* d_out, int out_size)
{
    const float* query = (const float*)d_in[0];
    const float* key   = (const float*)d_in[1];
    const float* value = (const float*)d_in[2];
    const float* Wq  = (const float*)d_in[3];
    const float* bq  = (const float*)d_in[4];
    const float* Wk  = (const float*)d_in[5];
    const float* bk  = (const float*)d_in[6];
    const float* Wv  = (const float*)d_in[7];
    const float* bv  = (const float*)d_in[8];
    const float* Wo  = (const float*)d_in[9];
    const float* bo  = (const float*)d_in[10];
    const float* Wqc = (const float*)d_in[11];
    const float* bqc = (const float*)d_in[12];
    const float* Wkc = (const float*)d_in[13];
    const float* bkc = (const float*)d_in[14];
    const float* Wvc = (const float*)d_in[15];
    const float* bvc = (const float*)d_in[16];
    const float* nw_q = (const float*)d_in[17];
    const float* nw_k = (const float*)d_in[18];
    const float* nw_v = (const float*)d_in[19];
    const float* nw_o = (const float*)d_in[20];
    const float* temperature = (const float*)d_in[21];

    float *q, *k, *v, *attn_fb, *out_fb, *wct;
    __nv_bfloat16 *wh, *wl, *ih, *il, *qh, *ql, *kh, *kl, *vh, *vl, *aoh;
    cudaGetSymbolAddress((void**)&q,  g_q);
    cudaGetSymbolAddress((void**)&k,  g_k);
    cudaGetSymbolAddress((void**)&v,  g_v);
    cudaGetSymbolAddress((void**)&attn_fb, g_attn_fb);
    cudaGetSymbolAddress((void**)&out_fb,  g_out_fb);
    cudaGetSymbolAddress((void**)&wh, g_Wh);
    cudaGetSymbolAddress((void**)&wl, g_Wl);
    cudaGetSymbolAddress((void**)&wct, g_WcT);
    cudaGetSymbolAddress((void**)&ih, g_Ih);
    cudaGetSymbolAddress((void**)&il, g_Il);
    cudaGetSymbolAddress((void**)&qh, g_qh);
    cudaGetSymbolAddress((void**)&ql, g_ql);
    cudaGetSymbolAddress((void**)&kh, g_kh);
    cudaGetSymbolAddress((void**)&kl, g_kl);
    cudaGetSymbolAddress((void**)&vh, g_vh);
    cudaGetSymbolAddress((void**)&vl, g_vl);
    cudaGetSymbolAddress((void**)&aoh, g_aoh);

    const size_t NOUT = (size_t)MTOT * D_;
    const size_t NATT = (size_t)B_ * H_ * S_ * S_;
    float* out = (float*)d_out;
    float* out_ptr;
    float* attn_ptr;
    const size_t osz = (size_t)out_size;
    if (osz == NOUT + NATT)      { out_ptr = out;    attn_ptr = out + NOUT; }
    else if (osz == NOUT)        { out_ptr = out;    attn_ptr = attn_fb;    }
    else if (osz == NATT)        { out_ptr = out_fb; attn_ptr = out;        }
    else                         { out_ptr = out;    attn_ptr = out + NOUT; }

    const int SMEM_PROJ  = 2*65536 + 1024;
    const int SMEM_SCORE = 65536 + 2048 + 1024;
    const int SMEM_AV    = 2*24576 + 1024;
    cudaFuncSetAttribute(proj_hmma,   cudaFuncAttributeMaxDynamicSharedMemorySize, SMEM_PROJ);
    cudaFuncSetAttribute(scores_hmma, cudaFuncAttributeMaxDynamicSharedMemorySize, SMEM_SCORE);
    cudaFuncSetAttribute(attnv_hmma,  cudaFuncAttributeMaxDynamicSharedMemorySize, SMEM_AV);

    const size_t WSZ = (size_t)D_ * D_;
    const size_t ASZ = (size_t)MTOT * D_;

    // Prep
    split_w4<<<dim3(1024, 4), 256>>>((const float4*)Wq, (const float4*)Wk,
                                     (const float4*)Wv, (const float4*)Wo, wh, wl);
    split_act<<<dim3(4096, 3), 256>>>((const float4*)query, (const float4*)key, (const float4*)value);
    transp3<<<dim3(32, 32, 3), dim3(32, 8)>>>(Wqc, Wkc, Wvc);

    dim3 gproj(D_/128, MTOT/128);   // (8, 32)

    // Spiking projections (3-pass split)
    proj_hmma<<<gproj, 256, SMEM_PROJ>>>(ih,           il,           wh,         wl,         bq, nw_q, q, 1);
    proj_hmma<<<gproj, 256, SMEM_PROJ>>>(ih + ASZ,     il + ASZ,     wh + WSZ,   wl + WSZ,   bk, nw_k, k, 1);
    proj_hmma<<<gproj, 256, SMEM_PROJ>>>(ih + 2*ASZ,   il + 2*ASZ,   wh + 2*WSZ, wl + 2*WSZ, bv, nw_v, v, 1);

    // ECM compensation -> bf16 hi/lo
    comp_bf16<<<MTOT, 256>>>(q, wct,         bqc, qh, ql);
    comp_bf16<<<MTOT, 256>>>(k, wct + WSZ,   bkc, kh, kl);
    comp_bf16<<<MTOT, 256>>>(v, wct + 2*WSZ, bvc, vh, vl);

    // Attention: exp-scores + row sums, rinv, normalize + attnv
    scores_hmma<<<dim3(8, 8, B_*H_), 256, SMEM_SCORE>>>(qh, ql, kh, kl, temperature, attn_ptr);
    finalize_rinv<<<256, 256>>>();
    attnv_hmma<<<dim3(8, B_*H_), 256, SMEM_AV>>>(attn_ptr, vh, aoh);

    // Output projection (1-pass) + MTN
    proj_hmma<<<gproj, 256, SMEM_PROJ>>>(aoh, aoh, wh + 3*WSZ, wl + 3*WSZ, bo, nw_o, out_ptr, 0);
}

// round 5
// speedup vs baseline: 3.1241x; 1.0904x over previous
#include <cuda_runtime.h>
#include <cuda_bf16.h>
#include <cstdint>

#define B_  4
#define S_  1024
#define D_  1024
#define H_  16
#define HD_ 64
#define MTOT (B_*S_)        // 4096
#define NZR (64*1024)       // B*H*S rows of attn
#define WSZ_ ((size_t)D_*D_)
#define ASZ_ ((size_t)MTOT*D_)

// ---------------------------------------------------------------------------
// Static scratch
// ---------------------------------------------------------------------------
__device__ float g_q[MTOT*D_];
__device__ float g_k[MTOT*D_];
__device__ float g_v[MTOT*D_];
__device__ float g_attn_fb[(size_t)B_*H_*S_*S_];
__device__ float g_out_fb[MTOT*D_];
__device__ __nv_bfloat16 g_Wh[(size_t)4*D_*D_];
__device__ __nv_bfloat16 g_Wl[(size_t)4*D_*D_];
__device__ float g_WcT[(size_t)3*D_*D_];
__device__ __nv_bfloat16 g_Ih[(size_t)3*MTOT*D_];
__device__ __nv_bfloat16 g_Il[(size_t)3*MTOT*D_];
__device__ __nv_bfloat16 g_qh[MTOT*D_], g_ql[MTOT*D_];
__device__ __nv_bfloat16 g_kh[MTOT*D_], g_kl[MTOT*D_];
__device__ __nv_bfloat16 g_vh[MTOT*D_], g_vl[MTOT*D_];
__device__ __nv_bfloat16 g_aoh[MTOT*D_];
__device__ float g_rspart[(size_t)NZR*8];
__device__ float g_rinv[NZR];

// ---------------------------------------------------------------------------
// Helpers
// ---------------------------------------------------------------------------
__device__ __forceinline__ uint32_t smem_u32(const void* p) {
    uint32_t a;
    asm("{ .reg .u64 t; cvta.to.shared.u64 t, %1; cvt.u32.u64 %0, t; }" : "=r"(a) : "l"(p));
    return a;
}
__device__ __forceinline__ uint32_t swz(uint32_t off)   { return off ^ ((off >> 3) & 0x70); } // 128B rows
__device__ __forceinline__ uint32_t swz64(uint32_t off) { return off ^ ((off >> 3) & 0x30); } // 64B rows

__device__ __forceinline__ void ldsm4(uint32_t& r0, uint32_t& r1, uint32_t& r2, uint32_t& r3, uint32_t a) {
    asm volatile("ldmatrix.sync.aligned.m8n8.x4.shared.b16 {%0,%1,%2,%3}, [%4];"
                 : "=r"(r0), "=r"(r1), "=r"(r2), "=r"(r3) : "r"(a));
}
__device__ __forceinline__ void ldsm4t(uint32_t& r0, uint32_t& r1, uint32_t& r2, uint32_t& r3, uint32_t a) {
    asm volatile("ldmatrix.sync.aligned.m8n8.x4.trans.shared.b16 {%0,%1,%2,%3}, [%4];"
                 : "=r"(r0), "=r"(r1), "=r"(r2), "=r"(r3) : "r"(a));
}
__device__ __forceinline__ void mma16816(float* c, const uint32_t* a, const uint32_t* b) {
    asm volatile("mma.sync.aligned.m16n8k16.row.col.f32.bf16.bf16.f32 "
                 "{%0,%1,%2,%3}, {%4,%5,%6,%7}, {%8,%9}, {%0,%1,%2,%3};"
                 : "+f"(c[0]), "+f"(c[1]), "+f"(c[2]), "+f"(c[3])
                 : "r"(a[0]), "r"(a[1]), "r"(a[2]), "r"(a[3]), "r"(b[0]), "r"(b[1]));
}
__device__ __forceinline__ void cpasync16(uint32_t sdst, const void* g) {
    asm volatile("cp.async.ca.shared.global [%0], [%1], 16;" :: "r"(sdst), "l"(g) : "memory");
}
#define CP_COMMIT() asm volatile("cp.async.commit_group;" ::: "memory")
#define CP_WAIT0()  asm volatile("cp.async.wait_group 0;" ::: "memory")
#define CP_WAIT1()  asm volatile("cp.async.wait_group 1;" ::: "memory")

__device__ __forceinline__ void split2(float x, float y, uint32_t& hi, uint32_t& lo) {
    __nv_bfloat16 hx = __float2bfloat16(x), hy = __float2bfloat16(y);
    __nv_bfloat16 lx = __float2bfloat16(x - __bfloat162float(hx));
    __nv_bfloat16 ly = __float2bfloat16(y - __bfloat162float(hy));
    hi = ((uint32_t)__bfloat16_as_ushort(hy) << 16) | (uint32_t)__bfloat16_as_ushort(hx);
    lo = ((uint32_t)__bfloat16_as_ushort(ly) << 16) | (uint32_t)__bfloat16_as_ushort(lx);
}
__device__ __forceinline__ uint32_t pack_hi(float x, float y) {
    return ((uint32_t)__bfloat16_as_ushort(__float2bfloat16(y)) << 16)
         |  (uint32_t)__bfloat16_as_ushort(__float2bfloat16(x));
}
__device__ __forceinline__ float mtn_f(float x, float n0, float n1, float n2, float n3) {
    float mem = x * 0.5f;
    float s = 0.f;
    if (mem >= 1.f) { s += n0; mem -= 1.f; }
    if (mem >= 2.f) { s += n1; mem -= 2.f; }
    if (mem >= 3.f) { s += n2; mem -= 3.f; }
    if (mem >= 4.f) { s += n3; mem -= 4.f; }
    return s;
}

// ---------------------------------------------------------------------------
// Projection GEMM core: C = mtn(A @ W^T + bias).
// Block 128x128, 8 warps (2x4), K chunks of 32 (SW64 rows), double-buffered.
// Stage layout (32KB): Ah@0, Al@8K, Wh@16K, Wl@24K.
// ---------------------------------------------------------------------------
template<int NP3>
__device__ __forceinline__ void proj_core(
    const __nv_bfloat16* __restrict__ Ah, const __nv_bfloat16* __restrict__ Al,
    const __nv_bfloat16* __restrict__ Wh, const __nv_bfloat16* __restrict__ Wl,
    const float* __restrict__ bias, const float* __restrict__ nw,
    float* __restrict__ C)
{
    extern __shared__ char sraw[];
    const uint32_t sb0 = smem_u32(sraw);
    const uint32_t sbase = (sb0 + 1023) & ~1023u;
    const int tid = threadIdx.x, lane = tid & 31, wid = tid >> 5;
    const int wm = wid >> 2, wn = wid & 3;
    const int bm = blockIdx.y * 128, bn = blockIdx.x * 128;

    float acc[4][4][4];
    #pragma unroll
    for (int i = 0; i < 4; i++)
        #pragma unroll
        for (int j = 0; j < 4; j++)
            #pragma unroll
            for (int t = 0; t < 4; t++) acc[i][j][t] = 0.f;

    auto issue = [&](int c, int stg) {
        uint32_t base = sbase + stg * 32768;
        #pragma unroll
        for (int i = 0; i < 2; i++) {
            int idx = tid + i * 256, r = idx >> 2, seg = idx & 3;
            uint32_t off = swz64((uint32_t)(r * 64 + seg * 16));
            const size_t ga = (size_t)(bm + r) * D_ + c * 32 + seg * 8;
            const size_t gw = (size_t)(bn + r) * D_ + c * 32 + seg * 8;
            cpasync16(base + off, Ah + ga);
            cpasync16(base + 16384 + off, Wh + gw);
            if (NP3) {
                cpasync16(base + 8192 + off, Al + ga);
                cpasync16(base + 24576 + off, Wl + gw);
            }
        }
        CP_COMMIT();
    };
    auto compute = [&](int stg) {
        uint32_t aB = sbase + stg * 32768;
        uint32_t bB = aB + 16384;
        #pragma unroll
        for (int ks = 0; ks < 2; ks++) {
            const uint32_t colb = (uint32_t)(ks * 32 + ((lane >> 4) << 4));
            uint32_t ah[4][4], al[4][4], bh[4][2], bl[4][2];
            #pragma unroll
            for (int mi = 0; mi < 4; mi++) {
                uint32_t off = swz64((uint32_t)((wm * 64 + mi * 16 + (lane & 15)) * 64) + colb);
                ldsm4(ah[mi][0], ah[mi][1], ah[mi][2], ah[mi][3], aB + off);
                if (NP3) ldsm4(al[mi][0], al[mi][1], al[mi][2], al[mi][3], aB + 8192 + off);
            }
            #pragma unroll
            for (int g = 0; g < 2; g++) {
                uint32_t off = swz64((uint32_t)((wn * 32 + g * 16 + (lane & 15)) * 64) + colb);
                uint32_t r0, r1, r2, r3;
                ldsm4(r0, r1, r2, r3, bB + off);
                bh[g*2][0] = r0; bh[g*2][1] = r2; bh[g*2+1][0] = r1; bh[g*2+1][1] = r3;
                if (NP3) {
                    ldsm4(r0, r1, r2, r3, bB + 8192 + off);
                    bl[g*2][0] = r0; bl[g*2][1] = r2; bl[g*2+1][0] = r1; bl[g*2+1][1] = r3;
                }
            }
            #pragma unroll
            for (int mi = 0; mi < 4; mi++)
                #pragma unroll
                for (int nf = 0; nf < 4; nf++) {
                    mma16816(acc[mi][nf], ah[mi], bh[nf]);
                    if (NP3) {
                        mma16816(acc[mi][nf], ah[mi], bl[nf]);
                        mma16816(acc[mi][nf], al[mi], bh[nf]);
                    }
                }
        }
    };

    issue(0, 0);
    for (int c = 0; c < 32; c++) {
        const int stg = c & 1;
        if (c < 31) { issue(c + 1, stg ^ 1); CP_WAIT1(); }
        else CP_WAIT0();
        __syncthreads();
        compute(stg);
        __syncthreads();
    }

    const float n0 = nw[0]*0.25f, n1 = nw[1]*0.25f, n2 = nw[2]*0.25f, n3 = nw[3]*0.25f;
    const int gid = lane >> 2, tig = lane & 3;
    #pragma unroll
    for (int mi = 0; mi < 4; mi++) {
        const int row = bm + wm * 64 + mi * 16 + gid;
        #pragma unroll
        for (int nf = 0; nf < 4; nf++) {
            const int col = bn + wn * 32 + nf * 8 + tig * 2;
            float2 bb = *(const float2*)(bias + col);
            float v0 = mtn_f(acc[mi][nf][0] + bb.x, n0, n1, n2, n3);
            float v1 = mtn_f(acc[mi][nf][1] + bb.y, n0, n1, n2, n3);
            float v2 = mtn_f(acc[mi][nf][2] + bb.x, n0, n1, n2, n3);
            float v3 = mtn_f(acc[mi][nf][3] + bb.y, n0, n1, n2, n3);
            *(float2*)(C + (size_t)row * D_ + col) = make_float2(v0, v1);
            *(float2*)(C + (size_t)(row + 8) * D_ + col) = make_float2(v2, v3);
        }
    }
}

// Merged q/k/v spiking projections: grid (8, 32, 3)
__global__ __launch_bounds__(256, 2) void proj3_hmma(
    const float* __restrict__ bq, const float* __restrict__ bk, const float* __restrict__ bv,
    const float* __restrict__ nwq, const float* __restrict__ nwk, const float* __restrict__ nwv)
{
    const int z = blockIdx.z;
    const __nv_bfloat16* Ah = g_Ih + (size_t)z * ASZ_;
    const __nv_bfloat16* Al = g_Il + (size_t)z * ASZ_;
    const __nv_bfloat16* Wh = g_Wh + (size_t)z * WSZ_;
    const __nv_bfloat16* Wl = g_Wl + (size_t)z * WSZ_;
    const float* bias = (z == 0) ? bq : (z == 1) ? bk : bv;
    const float* nw   = (z == 0) ? nwq : (z == 1) ? nwk : nwv;
    float* C          = (z == 0) ? g_q : (z == 1) ? g_k : g_v;
    proj_core<1>(Ah, Al, Wh, Wl, bias, nw, C);
}

// Output projection (1-pass): grid (8, 32)
__global__ __launch_bounds__(256, 2) void projo_hmma(
    const float* __restrict__ bias, const float* __restrict__ nw, float* __restrict__ C)
{
    proj_core<0>(g_aoh, g_aoh, g_Wh + 3 * WSZ_, g_Wl + 3 * WSZ_, bias, nw, C);
}

// ---------------------------------------------------------------------------
// Scores + exp + partial row sums (3-pass, K=64 single shot), 128B-row SW128.
// grid (8 sk, 8 sq, 64 z). smem: qh|ql|kh|kl 16K each + spart 2K + 1K align
// ---------------------------------------------------------------------------
__global__ __launch_bounds__(256) void scores_hmma(
    const __nv_bfloat16* __restrict__ Qh, const __nv_bfloat16* __restrict__ Ql,
    const __nv_bfloat16* __restrict__ Kh, const __nv_bfloat16* __restrict__ Kl,
    const float* __restrict__ temp, float* __restrict__ attn)
{
    extern __shared__ char sraw[];
    const uint32_t sb0 = smem_u32(sraw);
    const uint32_t sbase = (sb0 + 1023) & ~1023u;
    char* sm = sraw + (sbase - sb0);
    const int tid = threadIdx.x, lane = tid & 31, wid = tid >> 5;
    const int wm = wid >> 2, wn = wid & 3;
    const int z = blockIdx.z, b = z >> 4, h = z & 15;
    const int sq0 = blockIdx.y * 128, sk0 = blockIdx.x * 128;

    #pragma unroll
    for (int i = 0; i < 4; i++) {
        int idx = tid + i * 256, r = idx >> 3, c8 = (idx & 7) * 8;
        uint32_t off = swz((uint32_t)(r * 128 + c8 * 2));
        const size_t gq = (size_t)(b * S_ + sq0 + r) * D_ + h * HD_ + c8;
        const size_t gk = (size_t)(b * S_ + sk0 + r) * D_ + h * HD_ + c8;
        cpasync16(sbase + off, Qh + gq);
        cpasync16(sbase + 16384 + off, Ql + gq);
        cpasync16(sbase + 32768 + off, Kh + gk);
        cpasync16(sbase + 49152 + off, Kl + gk);
    }
    CP_COMMIT(); CP_WAIT0();
    __syncthreads();

    float acc[4][4][4];
    #pragma unroll
    for (int i = 0; i < 4; i++)
        #pragma unroll
        for (int j = 0; j < 4; j++)
            #pragma unroll
            for (int t = 0; t < 4; t++) acc[i][j][t] = 0.f;

    const uint32_t aB = sbase, bB = sbase + 32768;
    #pragma unroll
    for (int ks = 0; ks < 4; ks++) {
        const uint32_t kcol = (uint32_t)((ks * 16 + ((lane >> 4) << 3)) * 2);
        uint32_t ah[4][4], al[4][4], bh[4][2], bl[4][2];
        #pragma unroll
        for (int mi = 0; mi < 4; mi++) {
            uint32_t off = swz((uint32_t)((wm * 64 + mi * 16 + (lane & 15)) * 128) + kcol);
            ldsm4(ah[mi][0], ah[mi][1], ah[mi][2], ah[mi][3], aB + off);
            ldsm4(al[mi][0], al[mi][1], al[mi][2], al[mi][3], aB + 16384 + off);
        }
        #pragma unroll
        for (int g = 0; g < 2; g++) {
            uint32_t off = swz((uint32_t)((wn * 32 + g * 16 + (lane & 15)) * 128) + kcol);
            uint32_t r0, r1, r2, r3;
            ldsm4(r0, r1, r2, r3, bB + off);
            bh[g*2][0] = r0; bh[g*2][1] = r2; bh[g*2+1][0] = r1; bh[g*2+1][1] = r3;
            ldsm4(r0, r1, r2, r3, bB + 16384 + off);
            bl[g*2][0] = r0; bl[g*2][1] = r2; bl[g*2+1][0] = r1; bl[g*2+1][1] = r3;
        }
        #pragma unroll
        for (int mi = 0; mi < 4; mi++)
            #pragma unroll
            for (int nf = 0; nf < 4; nf++) {
                mma16816(acc[mi][nf], ah[mi], bh[nf]);
                mma16816(acc[mi][nf], ah[mi], bl[nf]);
                mma16816(acc[mi][nf], al[mi], bh[nf]);
            }
    }

    const float f = 0.125f / (temp[0] + 1e-8f);
    const int gid = lane >> 2, tig = lane & 3;
    float* spart = (float*)(sm + 65536);   // [4][128]
    #pragma unroll
    for (int mi = 0; mi < 4; mi++) {
        const int row = sq0 + wm * 64 + mi * 16 + gid;
        float* rp0 = attn + ((size_t)z * S_ + row) * S_;
        float* rp1 = rp0 + 8 * S_;
        float s0 = 0.f, s1 = 0.f;
        #pragma unroll
        for (int nf = 0; nf < 4; nf++) {
            const int col = sk0 + wn * 32 + nf * 8 + tig * 2;
            float e0 = expf(acc[mi][nf][0] * f);
            float e1 = expf(acc[mi][nf][1] * f);
            float e2 = expf(acc[mi][nf][2] * f);
            float e3 = expf(acc[mi][nf][3] * f);
            *(float2*)(rp0 + col) = make_float2(e0, e1);
            *(float2*)(rp1 + col) = make_float2(e2, e3);
            s0 += e0 + e1; s1 += e2 + e3;
        }
        s0 += __shfl_xor_sync(0xffffffffu, s0, 1);
        s0 += __shfl_xor_sync(0xffffffffu, s0, 2);
        s1 += __shfl_xor_sync(0xffffffffu, s1, 1);
        s1 += __shfl_xor_sync(0xffffffffu, s1, 2);
        if (tig == 0) {
            spart[wn * 128 + wm * 64 + mi * 16 + gid]     = s0;
            spart[wn * 128 + wm * 64 + mi * 16 + gid + 8] = s1;
        }
    }
    __syncthreads();
    if (tid < 128) {
        float s = (spart[tid] + spart[128 + tid]) + (spart[256 + tid] + spart[384 + tid]);
        g_rspart[((size_t)z * S_ + sq0 + tid) * 8 + blockIdx.x] = s;
    }
}

__global__ __launch_bounds__(256) void finalize_rinv()
{
    int row = blockIdx.x * 256 + threadIdx.x;
    const float4* p = (const float4*)(g_rspart + (size_t)row * 8);
    float4 a = p[0], bv = p[1];
    float s = ((a.x + a.y) + (a.z + a.w)) + ((bv.x + bv.y) + (bv.z + bv.w));
    g_rinv[row] = 1.f / s;
}

// ---------------------------------------------------------------------------
// attnv: normalize e -> w (write back), out = w @ V (bf16 hi)
// Block 128x64, warps 4x2, K chunks 64, 128B-row SW128 smem.
// ---------------------------------------------------------------------------
__global__ __launch_bounds__(256) void attnv_hmma(
    float* __restrict__ attn, const __nv_bfloat16* __restrict__ Vh,
    __nv_bfloat16* __restrict__ aoh)
{
    extern __shared__ char sraw[];
    const uint32_t sb0 = smem_u32(sraw);
    const uint32_t sbase = (sb0 + 1023) & ~1023u;
    char* sm = sraw + (sbase - sb0);
    const int tid = threadIdx.x, lane = tid & 31, wid = tid >> 5;
    const int wm = wid >> 1, wn = wid & 1;
    const int z = blockIdx.y, b = z >> 4, h = z & 15;
    const int sq0 = blockIdx.x * 128;

    float acc[2][4][4];
    #pragma unroll
    for (int i = 0; i < 2; i++)
        #pragma unroll
        for (int j = 0; j < 4; j++)
            #pragma unroll
            for (int t = 0; t < 4; t++) acc[i][j][t] = 0.f;

    float rinv8[8];
    #pragma unroll
    for (int i = 0; i < 8; i++)
        rinv8[i] = g_rinv[(size_t)z * S_ + sq0 + (tid >> 4) + i * 16];

    float4 av[8];
    auto ldgA = [&](int c) {
        #pragma unroll
        for (int i = 0; i < 8; i++) {
            int r = (tid >> 4) + i * 16, c4 = (tid & 15) * 4;
            float* p = attn + ((size_t)z * S_ + sq0 + r) * S_ + c * 64 + c4;
            float4 v = *(const float4*)p;
            v.x *= rinv8[i]; v.y *= rinv8[i]; v.z *= rinv8[i]; v.w *= rinv8[i];
            *(float4*)p = v;
            av[i] = v;
        }
    };
    auto cpV = [&](int c, int stg) {
        uint32_t base = sbase + stg * 24576 + 16384;
        #pragma unroll
        for (int i = 0; i < 2; i++) {
            int idx = tid + i * 256, r = idx >> 3, c8 = (idx & 7) * 8;
            uint32_t off = swz((uint32_t)(r * 128 + c8 * 2));
            cpasync16(base + off, Vh + (size_t)(b * S_ + c * 64 + r) * D_ + h * HD_ + c8);
        }
        CP_COMMIT();
    };
    auto stsA = [&](int stg) {
        char* dst = sm + stg * 24576;
        #pragma unroll
        for (int i = 0; i < 8; i++) {
            int r = (tid >> 4) + i * 16, c4 = (tid & 15) * 4;
            uint32_t off = swz((uint32_t)(r * 128 + c4 * 2));
            *(uint2*)(dst + off) = make_uint2(pack_hi(av[i].x, av[i].y), pack_hi(av[i].z, av[i].w));
        }
    };
    auto compute = [&](int stg) {
        uint32_t aB = sbase + stg * 24576;
        uint32_t bB = aB + 16384;
        #pragma unroll
        for (int ks = 0; ks < 4; ks++) {
            const int kb = ks * 16;
            const uint32_t kcol = (uint32_t)((kb + ((lane >> 4) << 3)) * 2);
            uint32_t ah[2][4], bh[4][2];
            #pragma unroll
            for (int mi = 0; mi < 2; mi++) {
                uint32_t off = swz((uint32_t)((wm * 32 + mi * 16 + (lane & 15)) * 128) + kcol);
                ldsm4(ah[mi][0], ah[mi][1], ah[mi][2], ah[mi][3], aB + off);
            }
            #pragma unroll
            for (int g = 0; g < 2; g++) {
                uint32_t off = swz((uint32_t)((kb + (lane & 15)) * 128
                                 + (wn * 32 + g * 16 + ((lane >> 4) << 3)) * 2));
                uint32_t r0, r1, r2, r3;
                ldsm4t(r0, r1, r2, r3, bB + off);
                bh[g*2][0] = r0; bh[g*2][1] = r1; bh[g*2+1][0] = r2; bh[g*2+1][1] = r3;
            }
            #pragma unroll
            for (int mi = 0; mi < 2; mi++)
                #pragma unroll
                for (int nf = 0; nf < 4; nf++)
                    mma16816(acc[mi][nf], ah[mi], bh[nf]);
        }
    };

    ldgA(0); cpV(0, 0);
    stsA(0);
    CP_WAIT0(); __syncthreads();
    for (int c = 0; c < 16; c++) {
        const int stg = c & 1;
        if (c < 15) { ldgA(c + 1); cpV(c + 1, stg ^ 1); }
        compute(stg);
        if (c < 15) {
            stsA(stg ^ 1);
            CP_WAIT0(); __syncthreads();
        }
    }

    const int gid = lane >> 2, tig = lane & 3;
    #pragma unroll
    for (int mi = 0; mi < 2; mi++) {
        const int row = sq0 + wm * 32 + mi * 16 + gid;
        #pragma unroll
        for (int nf = 0; nf < 4; nf++) {
            const int col = h * HD_ + wn * 32 + nf * 8 + tig * 2;
            *(uint32_t*)(aoh + (size_t)(b * S_ + row) * D_ + col) = pack_hi(acc[mi][nf][0], acc[mi][nf][1]);
            *(uint32_t*)(aoh + (size_t)(b * S_ + row + 8) * D_ + col) = pack_hi(acc[mi][nf][2], acc[mi][nf][3]);
        }
    }
}

// ---------------------------------------------------------------------------
// Prep kernels
// ---------------------------------------------------------------------------
__global__ __launch_bounds__(256) void split_w4(
    const float4* __restrict__ W0, const float4* __restrict__ W1,
    const float4* __restrict__ W2, const float4* __restrict__ W3,
    __nv_bfloat16* __restrict__ Wh, __nv_bfloat16* __restrict__ Wl)
{
    const int t = blockIdx.y;
    const float4* W = (t == 0) ? W0 : (t == 1) ? W1 : (t == 2) ? W2 : W3;
    const size_t i = (size_t)blockIdx.x * 256 + threadIdx.x;
    float4 v = W[i];
    uint32_t h0, l0, h1, l1;
    split2(v.x, v.y, h0, l0);
    split2(v.z, v.w, h1, l1);
    const size_t o = (size_t)t * D_ * D_ / 4 + i;
    ((uint2*)Wh)[o] = make_uint2(h0, h1);
    ((uint2*)Wl)[o] = make_uint2(l0, l1);
}

__global__ __launch_bounds__(256) void split_act(
    const float4* __restrict__ s0, const float4* __restrict__ s1, const float4* __restrict__ s2)
{
    const int t = blockIdx.y;
    const float4* src = (t == 0) ? s0 : (t == 1) ? s1 : s2;
    const size_t i = (size_t)blockIdx.x * 256 + threadIdx.x;
    float4 v = src[i];
    uint32_t h0, l0, h1, l1;
    split2(v.x, v.y, h0, l0);
    split2(v.z, v.w, h1, l1);
    const size_t o = (size_t)t * MTOT * D_ / 4 + i;
    ((uint2*)g_Ih)[o] = make_uint2(h0, h1);
    ((uint2*)g_Il)[o] = make_uint2(l0, l1);
}

__global__ __launch_bounds__(256) void transp3(
    const float* __restrict__ A0, const float* __restrict__ A1, const float* __restrict__ A2)
{
    __shared__ float t[32][33];
    const int sel = blockIdx.z;
    const float* A = (sel == 0) ? A0 : (sel == 1) ? A1 : A2;
    float* At = g_WcT + (size_t)sel * D_ * D_;
    int x = blockIdx.x * 32 + threadIdx.x;
    int y0 = blockIdx.y * 32 + threadIdx.y;
    #pragma unroll
    for (int r = 0; r < 4; r++)
        t[threadIdx.y + r*8][threadIdx.x] = A[(size_t)(y0 + r*8) * D_ + x];
    __syncthreads();
    int x2 = blockIdx.y * 32 + threadIdx.x;
    int y2 = blockIdx.x * 32 + threadIdx.y;
    #pragma unroll
    for (int r = 0; r < 4; r++)
        At[(size_t)(y2 + r*8) * D_ + x2] = t[threadIdx.x][threadIdx.y + r*8];
}

// ---------------------------------------------------------------------------
// Merged ECM compensation for q/k/v: grid (MTOT, 3)
// ---------------------------------------------------------------------------
__global__ __launch_bounds__(256) void comp3_bf16(
    const float* __restrict__ bqc, const float* __restrict__ bkc, const float* __restrict__ bvc)
{
    __shared__ float row[1024];
    __shared__ int   nzi[1024];
    __shared__ float nzv[1024];
    __shared__ int   cnt;
    const int tid = threadIdx.x;
    const int z = blockIdx.y;
    const float* X  = (z == 0) ? g_q : (z == 1) ? g_k : g_v;
    const float* bc = (z == 0) ? bqc : (z == 1) ? bkc : bvc;
    __nv_bfloat16* Oh = (z == 0) ? g_qh : (z == 1) ? g_kh : g_vh;
    __nv_bfloat16* Ol = (z == 0) ? g_ql : (z == 1) ? g_kl : g_vl;
    const float* WcT = g_WcT + (size_t)z * WSZ_;

    const float* xr = X + (size_t)blockIdx.x * D_;
    if (tid == 0) cnt = 0;
    __syncthreads();
    for (int j = tid; j < D_; j += 256) {
        float v = xr[j];
        row[j] = v;
        if (v != 0.f) { int p = atomicAdd(&cnt, 1); nzi[p] = j; nzv[p] = v; }
    }
    __syncthreads();
    const int c = cnt;
    const size_t base = (size_t)blockIdx.x * D_;
    for (int n = tid; n < D_; n += 256) {
        float acc = row[n] + bc[n];
        for (int t = 0; t < c; t++)
            acc = fmaf(-nzv[t], WcT[(size_t)nzi[t] * D_ + n], acc);
        __nv_bfloat16 hh = __float2bfloat16(acc);
        Oh[base + n] = hh;
        Ol[base + n] = __float2bfloat16(acc - __bfloat162float(hh));
    }
}

// ---------------------------------------------------------------------------
// Launch
// ---------------------------------------------------------------------------
extern "C" void kernel_launch(void* const* d_in, const int* in_sizes, int n_in,
                              void* d_out, int out_size)
{
    const float* query = (const float*)d_in[0];
    const float* key   = (const float*)d_in[1];
    const float* value = (const float*)d_in[2];
    const float* Wq  = (const float*)d_in[3];
    const float* bq  = (const float*)d_in[4];
    const float* Wk  = (const float*)d_in[5];
    const float* bk  = (const float*)d_in[6];
    const float* Wv  = (const float*)d_in[7];
    const float* bv  = (const float*)d_in[8];
    const float* Wo  = (const float*)d_in[9];
    const float* bo  = (const float*)d_in[10];
    const float* Wqc = (const float*)d_in[11];
    const float* bqc = (const float*)d_in[12];
    const float* Wkc = (const float*)d_in[13];
    const float* bkc = (const float*)d_in[14];
    const float* Wvc = (const float*)d_in[15];
    const float* bvc = (const float*)d_in[16];
    const float* nw_q = (const float*)d_in[17];
    const float* nw_k = (const float*)d_in[18];
    const float* nw_v = (const float*)d_in[19];
    const float* nw_o = (const float*)d_in[20];
    const float* temperature = (const float*)d_in[21];

    float *attn_fb, *out_fb;
    __nv_bfloat16 *wh, *wl, *qh, *ql, *kh, *kl, *vh, *aoh;
    cudaGetSymbolAddress((void**)&attn_fb, g_attn_fb);
    cudaGetSymbolAddress((void**)&out_fb,  g_out_fb);
    cudaGetSymbolAddress((void**)&wh, g_Wh);
    cudaGetSymbolAddress((void**)&wl, g_Wl);
    cudaGetSymbolAddress((void**)&qh, g_qh);
    cudaGetSymbolAddress((void**)&ql, g_ql);
    cudaGetSymbolAddress((void**)&kh, g_kh);
    cudaGetSymbolAddress((void**)&kl, g_kl);
    cudaGetSymbolAddress((void**)&vh, g_vh);
    cudaGetSymbolAddress((void**)&aoh, g_aoh);

    const size_t NOUT = (size_t)MTOT * D_;
    const size_t NATT = (size_t)B_ * H_ * S_ * S_;
    float* out = (float*)d_out;
    float* out_ptr;
    float* attn_ptr;
    const size_t osz = (size_t)out_size;
    if (osz == NOUT + NATT)      { out_ptr = out;    attn_ptr = out + NOUT; }
    else if (osz == NOUT)        { out_ptr = out;    attn_ptr = attn_fb;    }
    else if (osz == NATT)        { out_ptr = out_fb; attn_ptr = out;        }
    else                         { out_ptr = out;    attn_ptr = out + NOUT; }

    const int SMEM_PROJ  = 2*32768 + 1024;
    const int SMEM_SCORE = 65536 + 2048 + 1024;
    const int SMEM_AV    = 2*24576 + 1024;
    cudaFuncSetAttribute(proj3_hmma,  cudaFuncAttributeMaxDynamicSharedMemorySize, SMEM_PROJ);
    cudaFuncSetAttribute(projo_hmma,  cudaFuncAttributeMaxDynamicSharedMemorySize, SMEM_PROJ);
    cudaFuncSetAttribute(scores_hmma, cudaFuncAttributeMaxDynamicSharedMemorySize, SMEM_SCORE);
    cudaFuncSetAttribute(attnv_hmma,  cudaFuncAttributeMaxDynamicSharedMemorySize, SMEM_AV);

    // Prep
    split_w4<<<dim3(1024, 4), 256>>>((const float4*)Wq, (const float4*)Wk,
                                     (const float4*)Wv, (const float4*)Wo, wh, wl);
    split_act<<<dim3(4096, 3), 256>>>((const float4*)query, (const float4*)key, (const float4*)value);
    transp3<<<dim3(32, 32, 3), dim3(32, 8)>>>(Wqc, Wkc, Wvc);

    // Spiking projections (merged, 3-pass split)
    proj3_hmma<<<dim3(8, 32, 3), 256, SMEM_PROJ>>>(bq, bk, bv, nw_q, nw_k, nw_v);

    // ECM compensation (merged) -> bf16 hi/lo
    comp3_bf16<<<dim3(MTOT, 3), 256>>>(bqc, bkc, bvc);

    // Attention: exp-scores + row sums, rinv, normalize + attnv
    scores_hmma<<<dim3(8, 8, B_*H_), 256, SMEM_SCORE>>>(qh, ql, kh, kl, temperature, attn_ptr);
    finalize_rinv<<<256, 256>>>();
    attnv_hmma<<<dim3(8, B_*H_), 256, SMEM_AV>>>(attn_ptr, vh, aoh);

    // Output projection (1-pass) + MTN
    projo_hmma<<<dim3(8, 32), 256, SMEM_PROJ>>>(bo, nw_o, out_ptr);
}